// round 1
// baseline (speedup 1.0000x reference)
#include <cuda_runtime.h>

#define TT 64
#define BB 128
#define HH 256
#define G4H 1024
#define NBLK 128
#define NTHR 256
#define KCH 16
#define NCHUNK 8   /* 128 K per block-slice / 16 */

// -------- persistent device scratch (no allocations allowed) --------
__device__ float g_p0[4*BB*G4H];   // layer0 gate partials [ks][b][col]
__device__ float g_p1[4*BB*G4H];   // layer1 gate partials
__device__ float g_h0s[BB*HH];     // layer0 carried hidden state
__device__ float g_c0s[BB*HH];
__device__ float g_h1s[BB*HH];     // layer1 carried hidden state
__device__ float g_c1s[BB*HH];
__device__ float g_h0n[BB*HH];     // layer0 fresh hidden (input to layer1 this step)
__device__ unsigned g_ctr;         // barrier arrival counter (self-resetting)
__device__ unsigned g_gen;         // barrier generation (monotonic, base-relative)

__device__ __forceinline__ float sigf(float v){ return 1.0f/(1.0f+__expf(-v)); }

// Software grid barrier. Generation counter is monotonic; each block compares
// against the generation observed at kernel entry (base), so the kernel is
// safe to replay from a CUDA graph. Arrival counter self-resets every barrier.
__device__ __forceinline__ void gridbar(unsigned base, int phase){
  __syncthreads();
  if (threadIdx.x == 0){
    __threadfence();
    unsigned old = atomicAdd(&g_ctr, 1u);
    if (old == (unsigned)(NBLK-1)){
      g_ctr = 0u;
      __threadfence();
      atomicAdd(&g_gen, 1u);
    } else {
      while ((*(volatile unsigned*)&g_gen) - base < (unsigned)phase){ __nanosleep(40); }
    }
    __threadfence();
  }
  __syncthreads();
}

struct GemmCtx {
  int b0;      // batch-row tile origin (64 rows)
  int lrow;    // loader lane: A-row / W-col local index 0..63
  int kq;      // loader lane: k quad 0..3
  int wcol;    // global gate column for this loader lane's weights
  int ty4;     // compute: first of 4 local rows
  int tx4;     // compute: first of 4 local cols
  int colout;  // compute: first of 4 contiguous global gate columns
};

// One 64x64 output tile over a 128-wide K-slice of the virtual K=512 input
// [Alo(256) ; Ahi(256)] against weights [Wlo ; Whi]. 4x4 register tile per
// thread, double-buffered smem, padded [64][17] layout (conflict-free STS,
// broadcast A reads, 2-way worst-case W reads). Activations via __ldcg
// (cross-block data must bypass L1 within a launch).
__device__ __forceinline__ void gemm_block(
    const float* __restrict__ Alo, const float* __restrict__ Ahi,
    const float* __restrict__ Wlo, const float* __restrict__ Whi,
    float* __restrict__ pout, int ks, const GemmCtx& c,
    float* As, float* Bs)
{
  float4 acc0 = make_float4(0.f,0.f,0.f,0.f);
  float4 acc1 = acc0, acc2 = acc0, acc3 = acc0;
  const int kbase = ks*128;
  float4 ra, rw;

  // prologue: chunk 0 -> buffer 0
  {
    int vk = kbase + c.kq*4;
    const float* Ap = Alo; const float* Wp = Wlo; int off = vk;
    if (vk >= HH){ Ap = Ahi; Wp = Whi; off = vk - HH; }
    ra = __ldcg((const float4*)(Ap + (c.b0 + c.lrow)*HH + off));
    rw = __ldg ((const float4*)(Wp + c.wcol*HH + off));
  }
  {
    float* a = As + c.lrow*17 + c.kq*4;
    a[0]=ra.x; a[1]=ra.y; a[2]=ra.z; a[3]=ra.w;
    float* w = Bs + c.lrow*17 + c.kq*4;
    w[0]=rw.x; w[1]=rw.y; w[2]=rw.z; w[3]=rw.w;
  }

  #pragma unroll 1
  for (int ch = 0; ch < NCHUNK; ch++){
    __syncthreads();
    if (ch < NCHUNK-1){
      int vk = kbase + (ch+1)*KCH + c.kq*4;
      const float* Ap = Alo; const float* Wp = Wlo; int off = vk;
      if (vk >= HH){ Ap = Ahi; Wp = Whi; off = vk - HH; }
      ra = __ldcg((const float4*)(Ap + (c.b0 + c.lrow)*HH + off));
      rw = __ldg ((const float4*)(Wp + c.wcol*HH + off));
    }
    const float* Ab = As + (ch&1)*1088;
    const float* Wb = Bs + (ch&1)*1088;
    #pragma unroll
    for (int k = 0; k < KCH; k++){
      float a0 = Ab[(c.ty4+0)*17+k];
      float a1 = Ab[(c.ty4+1)*17+k];
      float a2 = Ab[(c.ty4+2)*17+k];
      float a3 = Ab[(c.ty4+3)*17+k];
      float w0 = Wb[(c.tx4+0)*17+k];
      float w1 = Wb[(c.tx4+1)*17+k];
      float w2 = Wb[(c.tx4+2)*17+k];
      float w3 = Wb[(c.tx4+3)*17+k];
      acc0.x += a0*w0; acc0.y += a0*w1; acc0.z += a0*w2; acc0.w += a0*w3;
      acc1.x += a1*w0; acc1.y += a1*w1; acc1.z += a1*w2; acc1.w += a1*w3;
      acc2.x += a2*w0; acc2.y += a2*w1; acc2.z += a2*w2; acc2.w += a2*w3;
      acc3.x += a3*w0; acc3.y += a3*w1; acc3.z += a3*w2; acc3.w += a3*w3;
    }
    if (ch < NCHUNK-1){
      float* a = As + ((ch+1)&1)*1088 + c.lrow*17 + c.kq*4;
      a[0]=ra.x; a[1]=ra.y; a[2]=ra.z; a[3]=ra.w;
      float* w = Bs + ((ch+1)&1)*1088 + c.lrow*17 + c.kq*4;
      w[0]=rw.x; w[1]=rw.y; w[2]=rw.z; w[3]=rw.w;
    }
  }

  // epilogue: 4 STG.128 of partial sums  p[ks][row][col..col+3]
  float* pb = pout + (ks*BB + c.b0 + c.ty4)*G4H + c.colout;
  *(float4*)(pb + 0*G4H) = acc0;
  *(float4*)(pb + 1*G4H) = acc1;
  *(float4*)(pb + 2*G4H) = acc2;
  *(float4*)(pb + 3*G4H) = acc3;
}

// LSTM elementwise: sum 4 K-partials + biases for the 4 gate quadrants of one
// (b,j); conditional state update per ops. 32768 elements == exactly one per
// thread across the grid.
__device__ __forceinline__ void ew_layer(
    int t, const float* __restrict__ p,
    const float* __restrict__ bi, const float* __restrict__ bh,
    float* __restrict__ hstate, float* __restrict__ cstate,
    float* __restrict__ hdst, const int* __restrict__ ops)
{
  int e = blockIdx.x*NTHR + threadIdx.x;   // 0..32767
  int b = e >> 8;
  int j = e & (HH-1);
  float gs[4];
  #pragma unroll
  for (int q = 0; q < 4; q++){
    int col = q*HH + j;
    float s = __ldg(bi + col) + __ldg(bh + col);
    s += __ldcg(p + (0*BB + b)*G4H + col);
    s += __ldcg(p + (1*BB + b)*G4H + col);
    s += __ldcg(p + (2*BB + b)*G4H + col);
    s += __ldcg(p + (3*BB + b)*G4H + col);
    gs[q] = s;
  }
  float ig = sigf(gs[0]);
  float fg = sigf(gs[1]);
  float gg = tanhf(gs[2]);
  float og = sigf(gs[3]);
  float cp = cstate[e];
  float cn = fg*cp + ig*gg;
  float hn = og * tanhf(cn);
  hdst[e] = hn;                                   // fresh h (layer input / output)
  if (ops[t*BB + b] != 0){ hstate[e] = hn; cstate[e] = cn; }  // conditional carry
}

__global__ void __launch_bounds__(NTHR, 1) stacklstm_kernel(
    const float* __restrict__ x,   const int* __restrict__ ops,
    const float* __restrict__ Wih, const float* __restrict__ Whh,
    const float* __restrict__ bih, const float* __restrict__ bhh,
    float* __restrict__ out)
{
  __shared__ float As[2*1088];
  __shared__ float Bs[2*1088];

  const int tid = threadIdx.x;
  const int bid = blockIdx.x;
  const int ks = bid & 3;          // K-split slice 0..3
  const int rg = bid >> 2;
  const int r  = rg >> 4;          // row tile 0..1
  const int g  = rg & 15;          // col group 0..15 (16 j-values -> 64 gate cols)
  const int j0 = g*16;

  GemmCtx c;
  c.b0   = r*64;
  c.lrow = tid & 63;
  c.kq   = tid >> 6;
  c.wcol = (c.lrow >> 4)*HH + j0 + (c.lrow & 15);
  const int ty = tid >> 4, tx = tid & 15;
  c.ty4  = ty*4;
  c.tx4  = tx*4;
  c.colout = (tx >> 2)*HH + j0 + ((tx*4) & 15);

  unsigned base = 0;
  if (tid == 0) base = *(volatile unsigned*)&g_gen;
  int ph = 0;

  // zero carried states (stack starts at zeros); must redo every launch
  { int e = bid*NTHR + tid; g_h0s[e]=0.f; g_c0s[e]=0.f; g_h1s[e]=0.f; g_c1s[e]=0.f; }
  gridbar(base, ++ph);

  const float* Wih1 = Wih + G4H*HH;
  const float* Whh1 = Whh + G4H*HH;

  for (int t = 0; t < TT; t++){
    // layer0 gates: [x_t ; h0_state] @ [W_ih0 ; W_hh0]^T  (partials)
    gemm_block(x + t*BB*HH, g_h0s, Wih, Whh, g_p0, ks, c, As, Bs);
    gridbar(base, ++ph);
    // layer0 elementwise -> fresh h0 (g_h0n) + conditional state carry
    ew_layer(t, g_p0, bih, bhh, g_h0s, g_c0s, g_h0n, ops);
    gridbar(base, ++ph);
    // layer1 gates: [h0_new ; h1_state] @ [W_ih1 ; W_hh1]^T
    gemm_block(g_h0n, g_h1s, Wih1, Whh1, g_p1, ks, c, As, Bs);
    gridbar(base, ++ph);
    // layer1 elementwise -> output row t + conditional state carry.
    // No trailing barrier needed: next GEMM0 touches only x/h0s/p0, disjoint
    // from everything EW1 reads/writes; ordering of h1s vs GEMM1(t+1) is
    // enforced transitively by the next two barriers.
    ew_layer(t, g_p1, bih + G4H, bhh + G4H, g_h1s, g_c1s, out + t*BB*HH, ops);
  }
}

extern "C" void kernel_launch(void* const* d_in, const int* in_sizes, int n_in,
                              void* d_out, int out_size)
{
  const float* x   = (const float*)d_in[0];
  const int*   ops = (const int*)  d_in[1];
  const float* Wih = (const float*)d_in[2];
  const float* Whh = (const float*)d_in[3];
  const float* bih = (const float*)d_in[4];
  const float* bhh = (const float*)d_in[5];
  float* out = (float*)d_out;
  stacklstm_kernel<<<NBLK, NTHR>>>(x, ops, Wih, Whh, bih, bhh, out);
}

// round 2
// speedup vs baseline: 1.1030x; 1.1030x over previous
#include <cuda_runtime.h>

#define TT 64
#define BB 128
#define HH 256
#define G4H 1024
#define NBLK 128
#define NTHR 512
#define KCH 32
#define NCHUNK 4   /* 128-wide K slice / 32 */

// -------- persistent device scratch (no allocations allowed) --------
__device__ float g_p0[4*BB*G4H];   // layer0 gate partials [ks][b][col]
__device__ float g_p1[4*BB*G4H];   // layer1 gate partials
__device__ float g_h0s[BB*HH];     // layer0 carried hidden state
__device__ float g_c0s[BB*HH];
__device__ float g_h1s[BB*HH];     // layer1 carried hidden state
__device__ float g_c1s[BB*HH];
__device__ float g_h0n[BB*HH];     // layer0 fresh hidden (input to layer1 this step)
__device__ unsigned g_ctr;         // barrier arrival counter (self-resetting)
__device__ unsigned g_gen;         // barrier generation (monotonic, base-relative)

__device__ __forceinline__ float sigf(float v){ return 1.0f/(1.0f+__expf(-v)); }

// Software grid barrier, graph-replay safe (monotonic generation vs entry base).
__device__ __forceinline__ void gridbar(unsigned base, int phase){
  __syncthreads();
  if (threadIdx.x == 0){
    __threadfence();
    unsigned old = atomicAdd(&g_ctr, 1u);
    if (old == (unsigned)(NBLK-1)){
      g_ctr = 0u;
      __threadfence();
      atomicAdd(&g_gen, 1u);
    } else {
      while ((*(volatile unsigned*)&g_gen) - base < (unsigned)phase){ __nanosleep(40); }
    }
    __threadfence();
  }
  __syncthreads();
}

struct GemmCtx {
  int b0;      // batch-row tile origin (64 rows)
  int lr;      // loader: A-row / W-col local index 0..63
  int kq;      // loader: k quad 0..7 (covers kq*4..kq*4+3 of the 32-chunk)
  int wcol;    // global gate column for this loader lane's weights
  int ty4;     // compute: first of 4 local rows
  int tx2;     // compute: first of 2 local cols
  int gcol;    // compute: first of 2 contiguous global gate cols for epilogue
};

// 64x64 output tile over a 128-wide K-slice of virtual K=512 = [Alo;Ahi] vs
// [Wlo;Whi]. Smem stored TRANSPOSED [k][64] so compute does 1 LDS.128 (A,
// broadcast within warp) + 1 LDS.64 (W, conflict-free) per k. 512 threads,
// 4x2 register tile, KCH=32 double-buffered chunks.
__device__ __forceinline__ void gemm_block(
    const float* __restrict__ Alo, const float* __restrict__ Ahi,
    const float* __restrict__ Wlo, const float* __restrict__ Whi,
    float* __restrict__ pout, int ks, const GemmCtx& c,
    float* As, float* Bs)  // each 2 * (KCH*64) floats
{
  float2 acc0 = make_float2(0.f,0.f);
  float2 acc1 = acc0, acc2 = acc0, acc3 = acc0;
  const int kbase = ks*128;
  float4 ra, rw;

  // prologue: chunk 0 -> buffer 0
  {
    int vk = kbase + c.kq*4;
    const float* Ap = Alo; const float* Wp = Wlo; int off = vk;
    if (vk >= HH){ Ap = Ahi; Wp = Whi; off = vk - HH; }
    ra = __ldcg((const float4*)(Ap + (c.b0 + c.lr)*HH + off));
    rw = __ldg ((const float4*)(Wp + c.wcol*HH + off));
  }
  {
    float* a = As + c.kq*4*64 + c.lr;   // transposed scatter, conflict-free
    a[0]=ra.x; a[64]=ra.y; a[128]=ra.z; a[192]=ra.w;
    float* w = Bs + c.kq*4*64 + c.lr;
    w[0]=rw.x; w[64]=rw.y; w[128]=rw.z; w[192]=rw.w;
  }

  #pragma unroll 1
  for (int ch = 0; ch < NCHUNK; ch++){
    __syncthreads();
    if (ch < NCHUNK-1){
      int vk = kbase + (ch+1)*KCH + c.kq*4;
      const float* Ap = Alo; const float* Wp = Wlo; int off = vk;
      if (vk >= HH){ Ap = Ahi; Wp = Whi; off = vk - HH; }
      ra = __ldcg((const float4*)(Ap + (c.b0 + c.lr)*HH + off));
      rw = __ldg ((const float4*)(Wp + c.wcol*HH + off));
    }
    const float* Ab = As + (ch&1)*(KCH*64);
    const float* Wb = Bs + (ch&1)*(KCH*64);
    #pragma unroll
    for (int k = 0; k < KCH; k++){
      float4 a = *(const float4*)(Ab + k*64 + c.ty4);
      float2 w = *(const float2*)(Wb + k*64 + c.tx2);
      acc0.x += a.x*w.x; acc0.y += a.x*w.y;
      acc1.x += a.y*w.x; acc1.y += a.y*w.y;
      acc2.x += a.z*w.x; acc2.y += a.z*w.y;
      acc3.x += a.w*w.x; acc3.y += a.w*w.y;
    }
    if (ch < NCHUNK-1){
      float* a = As + ((ch+1)&1)*(KCH*64) + c.kq*4*64 + c.lr;
      a[0]=ra.x; a[64]=ra.y; a[128]=ra.z; a[192]=ra.w;
      float* w = Bs + ((ch+1)&1)*(KCH*64) + c.kq*4*64 + c.lr;
      w[0]=rw.x; w[64]=rw.y; w[128]=rw.z; w[192]=rw.w;
    }
  }

  // epilogue: 4 STG.64 of partial sums  p[ks][row][gcol..gcol+1]
  float* pb = pout + (ks*BB + c.b0 + c.ty4)*G4H + c.gcol;
  *(float2*)(pb + 0*G4H) = acc0;
  *(float2*)(pb + 1*G4H) = acc1;
  *(float2*)(pb + 2*G4H) = acc2;
  *(float2*)(pb + 3*G4H) = acc3;
}

// LSTM elementwise: sum 4 K-partials + biases for the 4 gate quadrants of one
// (b,j); conditional state update per ops. 32768 elements; grid has 65536
// threads -> lower half active.
__device__ __forceinline__ void ew_layer(
    int t, const float* __restrict__ p,
    const float* __restrict__ bi, const float* __restrict__ bh,
    float* __restrict__ hstate, float* __restrict__ cstate,
    float* __restrict__ hdst, const int* __restrict__ ops)
{
  int e = blockIdx.x*NTHR + threadIdx.x;
  if (e >= BB*HH) return;
  int b = e >> 8;
  int j = e & (HH-1);
  float gs[4];
  #pragma unroll
  for (int q = 0; q < 4; q++){
    int col = q*HH + j;
    float s = __ldg(bi + col) + __ldg(bh + col);
    s += __ldcg(p + (0*BB + b)*G4H + col);
    s += __ldcg(p + (1*BB + b)*G4H + col);
    s += __ldcg(p + (2*BB + b)*G4H + col);
    s += __ldcg(p + (3*BB + b)*G4H + col);
    gs[q] = s;
  }
  float ig = sigf(gs[0]);
  float fg = sigf(gs[1]);
  float gg = tanhf(gs[2]);
  float og = sigf(gs[3]);
  float cp = cstate[e];
  float cn = fg*cp + ig*gg;
  float hn = og * tanhf(cn);
  hdst[e] = hn;                                   // fresh h (layer input / output)
  if (ops[t*BB + b] != 0){ hstate[e] = hn; cstate[e] = cn; }  // conditional carry
}

__global__ void __launch_bounds__(NTHR, 1) stacklstm_kernel(
    const float* __restrict__ x,   const int* __restrict__ ops,
    const float* __restrict__ Wih, const float* __restrict__ Whh,
    const float* __restrict__ bih, const float* __restrict__ bhh,
    float* __restrict__ out)
{
  __shared__ float As[2*KCH*64];
  __shared__ float Bs[2*KCH*64];

  const int tid = threadIdx.x;
  const int bid = blockIdx.x;
  const int ks = bid & 3;          // K-split slice 0..3
  const int rg = bid >> 2;
  const int r  = rg >> 4;          // row tile 0..1
  const int g  = rg & 15;          // col group 0..15 (16 j-values -> 64 gate cols)
  const int j0 = g*16;

  GemmCtx c;
  c.b0   = r*64;
  c.lr   = tid & 63;
  c.kq   = tid >> 6;               // 0..7
  c.wcol = (c.lr >> 4)*HH + j0 + (c.lr & 15);
  const int ty = tid >> 5, tx = tid & 31;   // 16 x 32
  c.ty4  = ty*4;
  c.tx2  = tx*2;
  c.gcol = ((tx*2) >> 4)*HH + j0 + ((tx*2) & 15);

  unsigned base = 0;
  if (tid == 0) base = *(volatile unsigned*)&g_gen;
  int ph = 0;

  // zero carried states (stack starts at zeros); must redo every launch
  { int e = bid*NTHR + tid;
    if (e < BB*HH){ g_h0s[e]=0.f; g_c0s[e]=0.f; g_h1s[e]=0.f; g_c1s[e]=0.f; } }
  gridbar(base, ++ph);

  const float* Wih1 = Wih + G4H*HH;
  const float* Whh1 = Whh + G4H*HH;

  for (int t = 0; t < TT; t++){
    // layer0 gates: [x_t ; h0_state] @ [W_ih0 ; W_hh0]^T  (partials)
    gemm_block(x + t*BB*HH, g_h0s, Wih, Whh, g_p0, ks, c, As, Bs);
    gridbar(base, ++ph);
    // layer0 elementwise -> fresh h0 (g_h0n) + conditional state carry
    ew_layer(t, g_p0, bih, bhh, g_h0s, g_c0s, g_h0n, ops);
    gridbar(base, ++ph);
    // layer1 gates: [h0_new ; h1_state] @ [W_ih1 ; W_hh1]^T
    gemm_block(g_h0n, g_h1s, Wih1, Whh1, g_p1, ks, c, As, Bs);
    gridbar(base, ++ph);
    // layer1 elementwise -> output row t + conditional state carry.
    // No trailing barrier: next GEMM0 touches only x/h0s/p0, all disjoint from
    // EW1's footprint; h1s ordering vs GEMM1(t+1) is transitively enforced.
    ew_layer(t, g_p1, bih + G4H, bhh + G4H, g_h1s, g_c1s, out + t*BB*HH, ops);
  }
}

extern "C" void kernel_launch(void* const* d_in, const int* in_sizes, int n_in,
                              void* d_out, int out_size)
{
  const float* x   = (const float*)d_in[0];
  const int*   ops = (const int*)  d_in[1];
  const float* Wih = (const float*)d_in[2];
  const float* Whh = (const float*)d_in[3];
  const float* bih = (const float*)d_in[4];
  const float* bhh = (const float*)d_in[5];
  float* out = (float*)d_out;
  stacklstm_kernel<<<NBLK, NTHR>>>(x, ops, Wih, Whh, bih, bhh, out);
}

// round 3
// speedup vs baseline: 1.1718x; 1.0624x over previous
#include <cuda_runtime.h>

#define TT 64
#define BB 128
#define HH 256
#define G4H 1024
#define NBLK 128
#define NTHR 128
#define KCH 32
#define NCHUNK 16
#define APAD 36

typedef unsigned long long u64;

// -------- persistent device scratch (no allocations allowed) --------
__device__ float g_h0s[2][BB*HH];  // layer0 h-state, parity double-buffered
__device__ float g_h1s[2][BB*HH];  // layer1 h-state
__device__ float g_h0n[BB*HH];     // fresh layer0 hidden (input to layer1)
__device__ unsigned g_ctr;         // barrier arrival counter (self-resetting)
__device__ unsigned g_gen;         // barrier generation (monotonic)

__device__ __forceinline__ float sigf(float v){ return 1.0f/(1.0f+__expf(-v)); }

// packed fp32x2 FMA (sm_100+; ptxas never auto-emits this)
__device__ __forceinline__ u64 ffma2(u64 a, u64 b, u64 c){
  u64 d; asm("fma.rn.f32x2 %0, %1, %2, %3;" : "=l"(d) : "l"(a), "l"(b), "l"(c));
  return d;
}
__device__ __forceinline__ float f2sum(u64 v){
  return __uint_as_float((unsigned)(v & 0xffffffffu)) +
         __uint_as_float((unsigned)(v >> 32));
}

// Software grid barrier, graph-replay safe (monotonic generation vs entry base).
__device__ __forceinline__ void gridbar(unsigned base, int phase){
  __syncthreads();
  if (threadIdx.x == 0){
    __threadfence();
    unsigned old = atomicAdd(&g_ctr, 1u);
    if (old == (unsigned)(NBLK-1)){
      g_ctr = 0u;
      __threadfence();
      atomicAdd(&g_gen, 1u);
    } else {
      while ((*(volatile unsigned*)&g_gen) - base < (unsigned)phase){ __nanosleep(20); }
    }
    __threadfence();
  }
  __syncthreads();
}

struct Smem {
  float As[2][32*APAD];   // A tile, row-major [row][KCH+4]
  float Wk[2][8*128];     // W tile, k-planes [kk][col*4+i] = W[col][kk*4+i]
  float gates[32*34];     // epilogue gate tile [row][col]
  float bsum[2][32];      // per-layer bias sums for owned gate cols
  float csh[2][256];      // c-state (block-private, smem-resident)
  float hsh[2][256];      // h-state shadow (for hold on op=0)
};

// 32x32 gate tile over full K=512 = [Alo(256); Ahi(256)] vs [Wlo; Whi].
// 128 threads, per-thread 4 rows x 2 cols {tx, tx+16}, k-pair-packed f32x2
// accumulators. Double-buffered KCH=32 chunks.
__device__ __forceinline__ void gemm32(
    const float* __restrict__ Alo, const float* __restrict__ Ahi,
    const float* __restrict__ Wlo, const float* __restrict__ Whi,
    Smem* sm, int b0, int lr, int kq, int wrow, int ty4, int tx,
    u64 acc[8])
{
  float4 ra0, ra1, rw0, rw1;
  // prologue: chunk 0 (lo half, k-offset 0)
  {
    const float* Ap = Alo + (b0+lr)*HH + kq*4;
    ra0 = __ldcg((const float4*)Ap);
    ra1 = __ldcg((const float4*)(Ap+16));
    const float* Wp = Wlo + wrow*HH + kq*4;
    rw0 = __ldg((const float4*)Wp);
    rw1 = __ldg((const float4*)(Wp+16));
  }
  *(float4*)(sm->As[0] + lr*APAD + kq*4)        = ra0;
  *(float4*)(sm->As[0] + lr*APAD + 16 + kq*4)   = ra1;
  *(float4*)(sm->Wk[0] + kq*128 + lr*4)         = rw0;
  *(float4*)(sm->Wk[0] + (kq+4)*128 + lr*4)     = rw1;

  #pragma unroll 1
  for (int ch = 0; ch < NCHUNK; ch++){
    __syncthreads();
    if (ch < NCHUNK-1){
      int ck = (ch+1)*KCH;
      const float* Ap; const float* Wp;
      if (ck < HH){ Ap = Alo + (b0+lr)*HH + ck + kq*4;      Wp = Wlo + wrow*HH + ck + kq*4; }
      else        { Ap = Ahi + (b0+lr)*HH + (ck-HH) + kq*4; Wp = Whi + wrow*HH + (ck-HH) + kq*4; }
      ra0 = __ldcg((const float4*)Ap);  ra1 = __ldcg((const float4*)(Ap+16));
      rw0 = __ldg ((const float4*)Wp);  rw1 = __ldg ((const float4*)(Wp+16));
    }
    const float* Ab = sm->As[ch&1];
    const float* Wb = sm->Wk[ch&1];
    #pragma unroll
    for (int kk = 0; kk < 8; kk++){
      ulonglong2 a0 = *(const ulonglong2*)(Ab + (ty4+0)*APAD + kk*4);
      ulonglong2 a1 = *(const ulonglong2*)(Ab + (ty4+1)*APAD + kk*4);
      ulonglong2 a2 = *(const ulonglong2*)(Ab + (ty4+2)*APAD + kk*4);
      ulonglong2 a3 = *(const ulonglong2*)(Ab + (ty4+3)*APAD + kk*4);
      ulonglong2 w0 = *(const ulonglong2*)(Wb + kk*128 + tx*4);        // col tx
      ulonglong2 w1 = *(const ulonglong2*)(Wb + kk*128 + 64 + tx*4);   // col tx+16
      acc[0]=ffma2(a0.x,w0.x,acc[0]); acc[0]=ffma2(a0.y,w0.y,acc[0]);
      acc[1]=ffma2(a0.x,w1.x,acc[1]); acc[1]=ffma2(a0.y,w1.y,acc[1]);
      acc[2]=ffma2(a1.x,w0.x,acc[2]); acc[2]=ffma2(a1.y,w0.y,acc[2]);
      acc[3]=ffma2(a1.x,w1.x,acc[3]); acc[3]=ffma2(a1.y,w1.y,acc[3]);
      acc[4]=ffma2(a2.x,w0.x,acc[4]); acc[4]=ffma2(a2.y,w0.y,acc[4]);
      acc[5]=ffma2(a2.x,w1.x,acc[5]); acc[5]=ffma2(a2.y,w1.y,acc[5]);
      acc[6]=ffma2(a3.x,w0.x,acc[6]); acc[6]=ffma2(a3.y,w0.y,acc[6]);
      acc[7]=ffma2(a3.x,w1.x,acc[7]); acc[7]=ffma2(a3.y,w1.y,acc[7]);
    }
    if (ch < NCHUNK-1){
      int nb = (ch+1)&1;
      *(float4*)(sm->As[nb] + lr*APAD + kq*4)      = ra0;
      *(float4*)(sm->As[nb] + lr*APAD + 16 + kq*4) = ra1;
      *(float4*)(sm->Wk[nb] + kq*128 + lr*4)       = rw0;
      *(float4*)(sm->Wk[nb] + (kq+4)*128 + lr*4)   = rw1;
    }
  }
}

// Fused LSTM elementwise from smem gates. Each block owns (32 batch x 8 j).
__device__ __forceinline__ void ew(
    Smem* sm, int l, int t, int b0, int j0, int tid,
    const int* __restrict__ ops,
    float* __restrict__ hdst, float* __restrict__ hnext)
{
  __syncthreads();   // gates tile complete
  #pragma unroll
  for (int e = tid; e < 256; e += NTHR){
    int b = e >> 3, jj = e & 7;
    float gi = sm->gates[b*34 + jj]      + sm->bsum[l][jj];
    float gf = sm->gates[b*34 + 8 + jj]  + sm->bsum[l][8+jj];
    float gg = sm->gates[b*34 + 16 + jj] + sm->bsum[l][16+jj];
    float go = sm->gates[b*34 + 24 + jj] + sm->bsum[l][24+jj];
    float cp = sm->csh[l][e];
    float cn = sigf(gf)*cp + sigf(gi)*tanhf(gg);
    float hn = sigf(go)*tanhf(cn);
    int op = __ldg(ops + t*BB + b0 + b);
    float hk = op ? hn : sm->hsh[l][e];
    float ck = op ? cn : cp;
    sm->csh[l][e] = ck;
    sm->hsh[l][e] = hk;
    int gidx = (b0+b)*HH + j0 + jj;
    hdst[gidx]  = hn;   // fresh hidden (layer input / output)
    hnext[gidx] = hk;   // carried state for next step (parity buffer)
  }
}

__global__ void __launch_bounds__(NTHR, 1) stacklstm_kernel(
    const float* __restrict__ x,   const int* __restrict__ ops,
    const float* __restrict__ Wih, const float* __restrict__ Whh,
    const float* __restrict__ bih, const float* __restrict__ bhh,
    float* __restrict__ out)
{
  __shared__ __align__(16) Smem sm;
  const int tid = threadIdx.x, bid = blockIdx.x;
  const int rt = bid >> 5;          // batch tile 0..3
  const int cg = bid & 31;          // col group 0..31 (8 j-values each)
  const int b0 = rt*32;
  const int j0 = cg*8;

  // loader mapping
  const int lr = tid >> 2;          // 0..31  (A row / local W col)
  const int kq = tid & 3;           // k quad within chunk half
  const int wrow = (lr >> 3)*HH + j0 + (lr & 7);   // global gate col = W row
  // compute mapping
  const int ty4 = (tid >> 4)*4;     // rows ty4..ty4+3
  const int tx  = tid & 15;         // cols tx, tx+16

  // bias sums (constant across steps)
  if (tid < 32){
    int gcol = (tid >> 3)*HH + j0 + (tid & 7);
    sm.bsum[0][tid] = __ldg(bih + gcol)       + __ldg(bhh + gcol);
    sm.bsum[1][tid] = __ldg(bih + G4H + gcol) + __ldg(bhh + G4H + gcol);
  }
  // zero block-private states
  #pragma unroll
  for (int i = tid; i < 256; i += NTHR){
    sm.csh[0][i]=0.f; sm.csh[1][i]=0.f; sm.hsh[0][i]=0.f; sm.hsh[1][i]=0.f;
  }
  // zero parity-0 global h states (read at t=0); stale from prior replay
  { int idx = bid*NTHR + tid;            // 0..16383
    g_h0s[0][idx]=0.f; g_h0s[0][idx+16384]=0.f;
    g_h1s[0][idx]=0.f; g_h1s[0][idx+16384]=0.f; }

  unsigned base = 0;
  if (tid == 0) base = *(volatile unsigned*)&g_gen;
  int ph = 0;
  gridbar(base, ++ph);

  const float* Wih1 = Wih + G4H*HH;
  const float* Whh1 = Whh + G4H*HH;

  for (int t = 0; t < TT; t++){
    const int p = t & 1;

    // ---- layer 0: gates = [x_t ; h0s(p)] @ [Wih0 ; Whh0]^T ----
    {
      u64 acc[8] = {0,0,0,0,0,0,0,0};
      gemm32(x + t*BB*HH, g_h0s[p], Wih, Whh, &sm, b0, lr, kq, wrow, ty4, tx, acc);
      #pragma unroll
      for (int r = 0; r < 4; r++){
        sm.gates[(ty4+r)*34 + tx]      = f2sum(acc[2*r+0]);
        sm.gates[(ty4+r)*34 + tx + 16] = f2sum(acc[2*r+1]);
      }
      ew(&sm, 0, t, b0, j0, tid, ops, g_h0n, g_h0s[p^1]);
    }
    gridbar(base, ++ph);   // h0n + h0s(p^1) visible

    // ---- layer 1: gates = [h0n ; h1s(p)] @ [Wih1 ; Whh1]^T ----
    {
      u64 acc[8] = {0,0,0,0,0,0,0,0};
      gemm32(g_h0n, g_h1s[p], Wih1, Whh1, &sm, b0, lr, kq, wrow, ty4, tx, acc);
      #pragma unroll
      for (int r = 0; r < 4; r++){
        sm.gates[(ty4+r)*34 + tx]      = f2sum(acc[2*r+0]);
        sm.gates[(ty4+r)*34 + tx + 16] = f2sum(acc[2*r+1]);
      }
      ew(&sm, 1, t, b0, j0, tid, ops, out + t*BB*HH, g_h1s[p^1]);
    }
    gridbar(base, ++ph);   // out row + h1s(p^1) visible
  }
}

extern "C" void kernel_launch(void* const* d_in, const int* in_sizes, int n_in,
                              void* d_out, int out_size)
{
  const float* x   = (const float*)d_in[0];
  const int*   ops = (const int*)  d_in[1];
  const float* Wih = (const float*)d_in[2];
  const float* Whh = (const float*)d_in[3];
  const float* bih = (const float*)d_in[4];
  const float* bhh = (const float*)d_in[5];
  float* out = (float*)d_out;
  stacklstm_kernel<<<NBLK, NTHR>>>(x, ops, Wih, Whh, bih, bhh, out);
}

// round 5
// speedup vs baseline: 1.9780x; 1.6880x over previous
#include <cuda_runtime.h>
#include <cstdint>
typedef uint32_t u32;

#define TT 64
#define BB 128
#define HH 256
#define G4H 1024
#define NBLK 128
#define NTHR 256
#define GSTR 132   /* fragment-group stride (floats): 128 + 4 pad to rotate banks */

// smem layout in floats
#define OF_B     0        /* B fragments: 2 nt * 64 kt * 32 lanes * 2 = 8192  */
#define OF_A     8192     /* A staging: 2 buffers * 64 groups * GSTR = 16896  */
#define OF_GATES 25088    /* 128 x 18 = 2304 */
#define OF_BSUM  27392    /* 16 */
#define SM_FLOATS 27412
#define SM_BYTES  (SM_FLOATS*4)

// persistent state (parity double-buffered)
__device__ float g_h0s[2][BB*HH];
__device__ float g_h1s[2][BB*HH];
__device__ float g_h0n[2][BB*HH];
__device__ unsigned g_ctr;
__device__ unsigned g_gen;

__device__ __forceinline__ float sigf(float v){ return 1.0f/(1.0f+__expf(-v)); }

__device__ __forceinline__ float tf32r(float v){
  float r; asm("cvt.rna.tf32.f32 %0, %1;" : "=f"(r) : "f"(v)); return r;
}
__device__ __forceinline__ float4 tf32r4(float4 v){
  return make_float4(tf32r(v.x), tf32r(v.y), tf32r(v.z), tf32r(v.w));
}

// m16n8k8 tf32 mma; A regs arrive as {a0,a2,a1,a3} (storage order) in a float4.
__device__ __forceinline__ void mma8(float* d, float4 a, float2 b){
  asm volatile("mma.sync.aligned.m16n8k8.row.col.f32.tf32.tf32.f32 "
    "{%0,%1,%2,%3}, {%4,%5,%6,%7}, {%8,%9}, {%0,%1,%2,%3};"
    : "+f"(d[0]),"+f"(d[1]),"+f"(d[2]),"+f"(d[3])
    : "r"(__float_as_uint(a.x)), "r"(__float_as_uint(a.z)),
      "r"(__float_as_uint(a.y)), "r"(__float_as_uint(a.w)),
      "r"(__float_as_uint(b.x)), "r"(__float_as_uint(b.y)));
}

// software grid barrier, graph-replay safe
__device__ __forceinline__ void gridbar(unsigned base, int phase){
  __syncthreads();
  if (threadIdx.x == 0){
    __threadfence();
    unsigned old = atomicAdd(&g_ctr, 1u);
    if (old == (unsigned)(NBLK-1)){
      g_ctr = 0u;
      __threadfence();
      atomicAdd(&g_gen, 1u);
    } else {
      while ((*(volatile unsigned*)&g_gen) - base < (unsigned)phase){ __nanosleep(20); }
    }
    __threadfence();
  }
  __syncthreads();
}

__global__ void __launch_bounds__(NTHR, 1) stacklstm_mma(
    const float* __restrict__ x,   const int* __restrict__ ops,
    const float* __restrict__ Wih, const float* __restrict__ Whh,
    const float* __restrict__ bih, const float* __restrict__ bhh,
    float* __restrict__ out)
{
  extern __shared__ float sm[];
  const int tid = threadIdx.x, bid = blockIdx.x;
  const int wid = tid >> 5, lane = tid & 31;
  const int layer = bid >> 6;          // 64 blocks per layer
  const int j0 = (bid & 63) * 4;       // 4 hidden indices per block (16 gate cols)

  const float* Wi = Wih + layer*G4H*HH;
  const float* Wh = Whh + layer*G4H*HH;

  // ---- B fragment setup (once): [nt(2)][kt(64)][lane(32)][2] ----
  // lane holds (k = kt*8 + lane&3, +4) for col n = nt*8 + lane>>2.
  for (int idx = tid; idx < 4096; idx += NTHR){
    int ln = idx & 31;
    int kt = (idx >> 5) & 63;
    int nt = idx >> 11;
    int n  = nt*8 + (ln>>2);
    int wrow = (n>>2)*HH + j0 + (n&3);   // gate = n>>2, jj = n&3
    int kk = kt*8 + (ln&3);
    const float* sw = (kk < HH) ? (Wi + wrow*HH + kk) : (Wh + wrow*HH + kk - HH);
    float b0 = tf32r(__ldg(sw));
    float b1 = tf32r(__ldg(sw + 4));
    *(float2*)(sm + OF_B + idx*2) = make_float2(b0, b1);
  }
  if (tid < 16){
    int wrow = (tid>>2)*HH + j0 + (tid&3);
    sm[OF_BSUM + tid] = __ldg(bih + layer*G4H + wrow) + __ldg(bhh + layer*G4H + wrow);
  }
  // zero parity-0 h states (read at t=0); one element per thread grid-wide
  { int idx = bid*NTHR + tid; g_h0s[0][idx] = 0.f; g_h1s[0][idx] = 0.f; }

  unsigned base = 0;
  if (tid == 0) base = *(volatile unsigned*)&g_gen;
  int ph = 0;
  gridbar(base, ++ph);

  // per-thread LSTM state: b = tid>>1, jj = (tid&1)*2 + {0,1}
  float cst[2] = {0.f, 0.f}, hk[2] = {0.f, 0.f};

  const int wr = wid >> 1, wc = wid & 1;      // warp grid 4x2
  const int skt = tid & 7, srb = tid >> 3;    // staging: kt, row base

  for (int p = 0; p <= TT; p++){
    const int t = layer ? (p-1) : p;
    const bool active = layer ? (p >= 1) : (p < TT);
    if (active){
      const float* Alo = layer ? g_h0n[t&1] : (x + t*BB*HH);
      const float* Ahi = layer ? g_h1s[t&1] : g_h0s[t&1];

      float acc0[4] = {0.f,0.f,0.f,0.f};
      float acc1[4] = {0.f,0.f,0.f,0.f};

      // prologue: stage chunk 0 into buffer 0
      {
        const float* src = Alo;
        #pragma unroll
        for (int i = 0; i < 4; i++){
          int r = srb + i*32;
          const float* rp = src + r*HH + skt*8;
          float4 v0 = tf32r4(__ldcg((const float4*)rp));
          float4 v1 = tf32r4(__ldcg((const float4*)(rp+4)));
          int lr = r & 15, half = lr >> 3, g = lr & 7, mt = r >> 4;
          float* gb = sm + OF_A + (mt*8 + skt)*GSTR + half*2;
          *(float2*)(gb + (g*4+0)*4) = make_float2(v0.x, v1.x);
          *(float2*)(gb + (g*4+1)*4) = make_float2(v0.y, v1.y);
          *(float2*)(gb + (g*4+2)*4) = make_float2(v0.z, v1.z);
          *(float2*)(gb + (g*4+3)*4) = make_float2(v0.w, v1.w);
        }
      }
      __syncthreads();

      #pragma unroll 1
      for (int ch = 0; ch < 8; ch++){
        // issue loads for next chunk (hide L2 latency under compute)
        float4 nv0[4], nv1[4];
        if (ch < 7){
          int nc = ch + 1;
          const float* src = (nc < 4) ? Alo : Ahi;
          int koff = (nc & 3) * 64;
          #pragma unroll
          for (int i = 0; i < 4; i++){
            int r = srb + i*32;
            const float* rp = src + r*HH + koff + skt*8;
            nv0[i] = __ldcg((const float4*)rp);
            nv1[i] = __ldcg((const float4*)(rp+4));
          }
        }
        // compute chunk ch
        const float* ab = sm + OF_A + (ch & 1)*8448;
        #pragma unroll
        for (int ktl = 0; ktl < 8; ktl++){
          int ktg = ch*8 + ktl;
          float4 a0 = *(const float4*)(ab + ((wr*2+0)*8 + ktl)*GSTR + lane*4);
          float4 a1 = *(const float4*)(ab + ((wr*2+1)*8 + ktl)*GSTR + lane*4);
          float2 bv = *(const float2*)(sm + OF_B + ((wc*64 + ktg)*32 + lane)*2);
          mma8(acc0, a0, bv);
          mma8(acc1, a1, bv);
        }
        // store next chunk into other buffer
        if (ch < 7){
          float* abn = sm + OF_A + ((ch+1) & 1)*8448;
          #pragma unroll
          for (int i = 0; i < 4; i++){
            int r = srb + i*32;
            float4 v0 = tf32r4(nv0[i]);
            float4 v1 = tf32r4(nv1[i]);
            int lr = r & 15, half = lr >> 3, g = lr & 7, mt = r >> 4;
            float* gb = abn + (mt*8 + skt)*GSTR + half*2;
            *(float2*)(gb + (g*4+0)*4) = make_float2(v0.x, v1.x);
            *(float2*)(gb + (g*4+1)*4) = make_float2(v0.y, v1.y);
            *(float2*)(gb + (g*4+2)*4) = make_float2(v0.z, v1.z);
            *(float2*)(gb + (g*4+3)*4) = make_float2(v0.w, v1.w);
          }
        }
        __syncthreads();
      }

      // epilogue: D fragments -> gates tile [128][18]
      {
        int g = lane >> 2, c2 = (lane & 3)*2;
        int cb = wc*8 + c2;
        float* gt = sm + OF_GATES;
        *(float2*)(gt + (wr*32 + 0*16 + g    )*18 + cb) = make_float2(acc0[0], acc0[1]);
        *(float2*)(gt + (wr*32 + 0*16 + g + 8)*18 + cb) = make_float2(acc0[2], acc0[3]);
        *(float2*)(gt + (wr*32 + 1*16 + g    )*18 + cb) = make_float2(acc1[0], acc1[1]);
        *(float2*)(gt + (wr*32 + 1*16 + g + 8)*18 + cb) = make_float2(acc1[2], acc1[3]);
      }
      __syncthreads();

      // fused LSTM elementwise: thread owns (b = tid>>1, jj = (tid&1)*2 + s)
      {
        const int b = tid >> 1, jb = (tid & 1)*2;
        const int op = __ldg(ops + t*BB + b);
        const float* gt = sm + OF_GATES + b*18;
        const float* bs = sm + OF_BSUM;
        float fresh[2], keep[2];
        #pragma unroll
        for (int s = 0; s < 2; s++){
          int jj = jb + s;
          float gi = gt[jj]      + bs[jj];
          float gf = gt[4 + jj]  + bs[4 + jj];
          float gg = gt[8 + jj]  + bs[8 + jj];
          float go = gt[12 + jj] + bs[12 + jj];
          float cn = sigf(gf)*cst[s] + sigf(gi)*tanhf(gg);
          float hn = sigf(go)*tanhf(cn);
          if (op){ cst[s] = cn; hk[s] = hn; }
          fresh[s] = hn;
          keep[s]  = hk[s];
        }
        float* fdst = layer ? (out + t*BB*HH)     : g_h0n[t&1];
        float* kdst = layer ? g_h1s[(t+1)&1]      : g_h0s[(t+1)&1];
        *(float2*)(fdst + b*HH + j0 + jb) = make_float2(fresh[0], fresh[1]);
        *(float2*)(kdst + b*HH + j0 + jb) = make_float2(keep[0],  keep[1]);
      }
    }
    gridbar(base, ++ph);
  }
}

extern "C" void kernel_launch(void* const* d_in, const int* in_sizes, int n_in,
                              void* d_out, int out_size)
{
  const float* x   = (const float*)d_in[0];
  const int*   ops = (const int*)  d_in[1];
  const float* Wih = (const float*)d_in[2];
  const float* Whh = (const float*)d_in[3];
  const float* bih = (const float*)d_in[4];
  const float* bhh = (const float*)d_in[5];
  float* out = (float*)d_out;
  static int inited = 0;
  if (!inited){
    cudaFuncSetAttribute(stacklstm_mma, cudaFuncAttributeMaxDynamicSharedMemorySize, SM_BYTES);
    inited = 1;
  }
  stacklstm_mma<<<NBLK, NTHR, SM_BYTES>>>(x, ops, Wih, Whh, bih, bhh, out);
}

// round 6
// speedup vs baseline: 1.9957x; 1.0089x over previous
#include <cuda_runtime.h>
#include <cstdint>

#define TT 64
#define BB 128
#define HH 256
#define G4H 1024
#define NBLK 128
#define NTHR 256
#define GSTR 132   /* fragment-group stride: 128 floats + 4 pad */

// smem layout (floats)
#define OF_B 0                       /* B frags: 2nt * 64ktg * 32 lanes * 2 = 8192 */
#define OF_A 8192                    /* A staging: 2 bufs * 64 groups * GSTR       */
#define SM_FLOATS (8192 + 2*64*GSTR)
#define SM_BYTES  (SM_FLOATS*4)

// persistent state (parity double-buffered)
__device__ float g_h0s[2][BB*HH];
__device__ float g_h1s[2][BB*HH];
__device__ float g_h0n[2][BB*HH];
__device__ unsigned g_ctr0, g_gen0;   // layer0 group (init round is 128-wide)
__device__ unsigned g_ctr1, g_gen1;   // layer1 group

__device__ __forceinline__ float sigf(float v){ return 1.0f/(1.0f+__expf(-v)); }
__device__ __forceinline__ float tf32r(float v){
  float r; asm("cvt.rna.tf32.f32 %0, %1;" : "=f"(r) : "f"(v)); return r;
}

// m16n8k8 tf32 mma; A float4 storage order (a0,a1,a2,a3)=(x,y,z,w) maps to PTX
// slots {a0,a1,a2,a3} = {x,z,y,w} (row-pair-major in PTX).
__device__ __forceinline__ void mma8(float* d, float4 a, float2 b){
  asm volatile("mma.sync.aligned.m16n8k8.row.col.f32.tf32.tf32.f32 "
    "{%0,%1,%2,%3}, {%4,%5,%6,%7}, {%8,%9}, {%0,%1,%2,%3};"
    : "+f"(d[0]),"+f"(d[1]),"+f"(d[2]),"+f"(d[3])
    : "r"(__float_as_uint(a.x)), "r"(__float_as_uint(a.z)),
      "r"(__float_as_uint(a.y)), "r"(__float_as_uint(a.w)),
      "r"(__float_as_uint(b.x)), "r"(__float_as_uint(b.y)));
}

// group barrier arrival (counter self-resets; gen monotonic)
__device__ __forceinline__ void arrive(unsigned* ctr, unsigned* gen, unsigned target){
  __syncthreads();
  if (threadIdx.x == 0){
    __threadfence();
    unsigned old = atomicAdd(ctr, 1u);
    if (old == target - 1u){
      *(volatile unsigned*)ctr = 0u;
      __threadfence();
      atomicAdd(gen, 1u);
    }
  }
}

__global__ void __launch_bounds__(NTHR, 1) stacklstm_mma(
    const float* __restrict__ x,   const int* __restrict__ ops,
    const float* __restrict__ Wih, const float* __restrict__ Whh,
    const float* __restrict__ bih, const float* __restrict__ bhh,
    float* __restrict__ out)
{
  extern __shared__ float smf[];
  const int tid = threadIdx.x, bid = blockIdx.x;
  const int wr = tid >> 5, lane = tid & 31;
  const int layer = bid >> 6;           // 64 blocks per layer group
  const int j0 = (bid & 63) * 4;        // 4 hidden indices (16 gate cols) per block

  const float* Wi = Wih + layer*G4H*HH;
  const float* Wh = Whh + layer*G4H*HH;

  // ---- B fragments (once): [nt(2)][ktg(64)][lane(32)] float2 ----
  for (int idx = tid; idx < 4096; idx += NTHR){
    int ln = idx & 31;
    int kt = (idx >> 5) & 63;
    int nt = idx >> 11;
    int n  = nt*8 + (ln >> 2);
    int wrow = (n >> 2)*HH + j0 + (n & 3);
    int kk = kt*8 + (ln & 3);
    const float* sw = (kk < HH) ? (Wi + wrow*HH + kk) : (Wh + wrow*HH + kk - HH);
    *(float2*)(smf + OF_B + idx*2) = make_float2(tf32r(__ldg(sw)), tf32r(__ldg(sw + 4)));
  }

  // per-thread constants
  const int q  = lane & 3;
  const int jj = (q >> 1) | ((q & 1) << 1);      // 0,2,1,3 for q=0..3
  const int b1 = wr*16 + (lane >> 2);            // cell rows b1, b1+8
  float biasv[4];
  #pragma unroll
  for (int g = 0; g < 4; g++){
    int wrow = g*HH + j0 + jj;
    biasv[g] = __ldg(bih + layer*G4H + wrow) + __ldg(bhh + layer*G4H + wrow);
  }
  const int srb = tid >> 3, skt = tid & 7;       // staging: row base, k-tile

  // zero parity-0 states (stack starts at zeros)
  { int idx = bid*NTHR + tid; g_h0s[0][idx] = 0.f; g_h1s[0][idx] = 0.f; }

  // bases read BEFORE our init arrival -> exact (init round needs all 128,
  // and gen1's first bump transitively requires every block's phase-0 wait).
  unsigned base0 = 0, base1 = 0;
  if (tid == 0){
    base0 = *(volatile unsigned*)&g_gen0;
    base1 = *(volatile unsigned*)&g_gen1;
  }
  arrive(&g_ctr0, &g_gen0, 128u);   // init round: ALL 128 blocks

  // register LSTM state: 2 cells (b1, jj) and (b1+8, jj)
  float c0 = 0.f, c1 = 0.f, hk0 = 0.f, hk1 = 0.f;

  for (int t = 0; t < TT; t++){
    const float* Alo = layer ? g_h0n[t&1] : (x + t*BB*HH);
    const float* Ahi = layer ? g_h1s[t&1] : g_h0s[t&1];

    if (layer == 0){
      // stage chunk0 (x side, no dependency) BEFORE the wait
      #pragma unroll
      for (int i = 0; i < 4; i++){
        int r = srb + i*32;
        const float* rp = Alo + r*HH + skt*8;
        float4 v0 = __ldcg((const float4*)rp);
        float4 v1 = __ldcg((const float4*)(rp+4));
        v0.x=tf32r(v0.x); v0.y=tf32r(v0.y); v0.z=tf32r(v0.z); v0.w=tf32r(v0.w);
        v1.x=tf32r(v1.x); v1.y=tf32r(v1.y); v1.z=tf32r(v1.z); v1.w=tf32r(v1.w);
        int lr = r & 15, half = lr >> 3, g = lr & 7, mt = r >> 4;
        float* gb = smf + OF_A + (mt*8 + skt)*GSTR + half*2;
        *(float2*)(gb + (g*4+0)*4) = make_float2(v0.x, v1.x);
        *(float2*)(gb + (g*4+1)*4) = make_float2(v0.y, v1.y);
        *(float2*)(gb + (g*4+2)*4) = make_float2(v0.z, v1.z);
        *(float2*)(gb + (g*4+3)*4) = make_float2(v0.w, v1.w);
      }
      if (tid == 0){
        while (*(volatile unsigned*)&g_gen0 - base0 < (unsigned)(t+1)) __nanosleep(30);
        if (t >= 2)
          while (*(volatile unsigned*)&g_gen1 - base1 < (unsigned)(t-1)) __nanosleep(30);
        __threadfence();
      }
      __syncthreads();
    } else {
      if (tid == 0){
        while (*(volatile unsigned*)&g_gen0 - base0 < (unsigned)(t+2)) __nanosleep(30);
        if (t >= 1)
          while (*(volatile unsigned*)&g_gen1 - base1 < (unsigned)(t)) __nanosleep(30);
        __threadfence();
      }
      __syncthreads();
      // stage chunk0 (h0n)
      #pragma unroll
      for (int i = 0; i < 4; i++){
        int r = srb + i*32;
        const float* rp = Alo + r*HH + skt*8;
        float4 v0 = __ldcg((const float4*)rp);
        float4 v1 = __ldcg((const float4*)(rp+4));
        v0.x=tf32r(v0.x); v0.y=tf32r(v0.y); v0.z=tf32r(v0.z); v0.w=tf32r(v0.w);
        v1.x=tf32r(v1.x); v1.y=tf32r(v1.y); v1.z=tf32r(v1.z); v1.w=tf32r(v1.w);
        int lr = r & 15, half = lr >> 3, g = lr & 7, mt = r >> 4;
        float* gb = smf + OF_A + (mt*8 + skt)*GSTR + half*2;
        *(float2*)(gb + (g*4+0)*4) = make_float2(v0.x, v1.x);
        *(float2*)(gb + (g*4+1)*4) = make_float2(v0.y, v1.y);
        *(float2*)(gb + (g*4+2)*4) = make_float2(v0.z, v1.z);
        *(float2*)(gb + (g*4+3)*4) = make_float2(v0.w, v1.w);
      }
      __syncthreads();
    }

    // ---- GEMM: D[128x16] += A[128x512] @ B^T over 8 K-chunks of 64 ----
    float acc0[4] = {0.f,0.f,0.f,0.f};   // n-tile 0 (cols 0-7)
    float acc1[4] = {0.f,0.f,0.f,0.f};   // n-tile 1 (cols 8-15)
    #pragma unroll 1
    for (int ch = 0; ch < 8; ch++){
      float4 nv0[4], nv1[4];
      if (ch < 7){
        int nc = ch + 1;
        const float* src = (nc < 4) ? Alo : Ahi;
        int koff = (nc & 3) * 64;
        #pragma unroll
        for (int i = 0; i < 4; i++){
          int r = srb + i*32;
          const float* rp = src + r*HH + koff + skt*8;
          nv0[i] = __ldcg((const float4*)rp);
          nv1[i] = __ldcg((const float4*)(rp+4));
        }
      }
      const float* ab = smf + OF_A + (ch & 1)*(64*GSTR) + wr*8*GSTR;
      #pragma unroll
      for (int ktl = 0; ktl < 8; ktl++){
        int ktg = ch*8 + ktl;
        float4 a  = *(const float4*)(ab + ktl*GSTR + lane*4);
        float2 bv0 = *(const float2*)(smf + OF_B + (ktg*32 + lane)*2);
        float2 bv1 = *(const float2*)(smf + OF_B + ((64 + ktg)*32 + lane)*2);
        mma8(acc0, a, bv0);
        mma8(acc1, a, bv1);
      }
      if (ch < 7){
        float* bufn = smf + OF_A + ((ch+1) & 1)*(64*GSTR);
        #pragma unroll
        for (int i = 0; i < 4; i++){
          float4 v0 = nv0[i], v1 = nv1[i];
          v0.x=tf32r(v0.x); v0.y=tf32r(v0.y); v0.z=tf32r(v0.z); v0.w=tf32r(v0.w);
          v1.x=tf32r(v1.x); v1.y=tf32r(v1.y); v1.z=tf32r(v1.z); v1.w=tf32r(v1.w);
          int r = srb + i*32;
          int lr = r & 15, half = lr >> 3, g = lr & 7, mt = r >> 4;
          float* gb = bufn + (mt*8 + skt)*GSTR + half*2;
          *(float2*)(gb + (g*4+0)*4) = make_float2(v0.x, v1.x);
          *(float2*)(gb + (g*4+1)*4) = make_float2(v0.y, v1.y);
          *(float2*)(gb + (g*4+2)*4) = make_float2(v0.z, v1.z);
          *(float2*)(gb + (g*4+3)*4) = make_float2(v0.w, v1.w);
        }
      }
      __syncthreads();
    }

    // ---- in-register gate exchange + LSTM elementwise ----
    // thread (q) holds cols {c, c+1, c+8, c+9} with c = q*2; bfly(xor=2)
    // exchanges the missing gate pair; lane then owns all 4 gates of jj.
    {
      float s0 = __shfl_xor_sync(0xffffffffu, (q < 2) ? acc0[1] : acc0[0], 2); // row b1,   nt0
      float s1 = __shfl_xor_sync(0xffffffffu, (q < 2) ? acc0[3] : acc0[2], 2); // row b1+8, nt0
      float s2 = __shfl_xor_sync(0xffffffffu, (q < 2) ? acc1[1] : acc1[0], 2); // row b1,   nt1
      float s3 = __shfl_xor_sync(0xffffffffu, (q < 2) ? acc1[3] : acc1[2], 2); // row b1+8, nt1
      float gi0, gf0, gg0, go0, gi1, gf1, gg1, go1;
      if (q < 2){
        gi0 = acc0[0]; gf0 = s0; gg0 = acc1[0]; go0 = s2;
        gi1 = acc0[2]; gf1 = s1; gg1 = acc1[2]; go1 = s3;
      } else {
        gi0 = s0; gf0 = acc0[1]; gg0 = s2; go0 = acc1[1];
        gi1 = s1; gf1 = acc0[3]; gg1 = s3; go1 = acc1[3];
      }
      gi0 += biasv[0]; gf0 += biasv[1]; gg0 += biasv[2]; go0 += biasv[3];
      gi1 += biasv[0]; gf1 += biasv[1]; gg1 += biasv[2]; go1 += biasv[3];

      const int op0 = __ldg(ops + t*BB + b1);
      const int op1 = __ldg(ops + t*BB + b1 + 8);
      float cn0 = sigf(gf0)*c0 + sigf(gi0)*tanhf(gg0);
      float hn0 = sigf(go0)*tanhf(cn0);
      float cn1 = sigf(gf1)*c1 + sigf(gi1)*tanhf(gg1);
      float hn1 = sigf(go1)*tanhf(cn1);
      if (op0){ c0 = cn0; hk0 = hn0; }
      if (op1){ c1 = cn1; hk1 = hn1; }

      float* fresh = layer ? (out + t*BB*HH)  : g_h0n[t&1];
      float* keep  = layer ? g_h1s[(t+1)&1]   : g_h0s[(t+1)&1];
      const int o0 = b1*HH + j0 + jj;
      const int o1 = o0 + 8*HH;
      fresh[o0] = hn0; fresh[o1] = hn1;
      keep[o0]  = hk0; keep[o1]  = hk1;
    }

    if (layer == 0) arrive(&g_ctr0, &g_gen0, 64u);
    else            arrive(&g_ctr1, &g_gen1, 64u);
  }
}

extern "C" void kernel_launch(void* const* d_in, const int* in_sizes, int n_in,
                              void* d_out, int out_size)
{
  const float* x   = (const float*)d_in[0];
  const int*   ops = (const int*)  d_in[1];
  const float* Wih = (const float*)d_in[2];
  const float* Whh = (const float*)d_in[3];
  const float* bih = (const float*)d_in[4];
  const float* bhh = (const float*)d_in[5];
  float* out = (float*)d_out;
  static int inited = 0;
  if (!inited){
    cudaFuncSetAttribute(stacklstm_mma, cudaFuncAttributeMaxDynamicSharedMemorySize, SM_BYTES);
    inited = 1;
  }
  stacklstm_mma<<<NBLK, NTHR, SM_BYTES>>>(x, ops, Wih, Whh, bih, bhh, out);
}

// round 7
// speedup vs baseline: 3.4151x; 1.7113x over previous
#include <cuda_runtime.h>
#include <cuda_fp16.h>
#include <cstdint>
typedef uint32_t u32;

#define TT 64
#define BB 128
#define HH 256
#define G4H 1024
#define NBLK 128
#define NTHR 256
#define KP 72            /* halves per row per 64-k chunk (64 + 8 pad) */

// dynamic smem layout (bytes)
#define OF_W 0                       /* W frags: [nt2][ktg32][lane32] uint2 = 16 KB */
#define OF_A 16384                   /* A bufs: 2 x 128 x KP halves = 36 KB         */
#define ABUF_BYTES (128*KP*2)
#define SM_BYTES (16384 + 2*ABUF_BYTES)

// persistent state (16B-aligned backing for LDG.128)
__device__ uint4 g_h0sB[2][BB*HH/8];
__device__ uint4 g_h1sB[2][BB*HH/8];
__device__ uint4 g_h0nB[2][BB*HH/8];
__device__ uint4 g_xhB[TT*BB*HH/8];   // fp16 copy of x
__device__ unsigned g_ctr0, g_gen0;   // layer0 group (init round is 128-wide)
__device__ unsigned g_ctr1, g_gen1;   // layer1 group

__device__ __forceinline__ float sigf(float v){ return 1.0f/(1.0f+__expf(-v)); }

// m16n8k16 fp16 mma, fp32 accum
__device__ __forceinline__ void hmma(float* d, u32 a0, u32 a1, u32 a2, u32 a3, uint2 b){
  asm volatile("mma.sync.aligned.m16n8k16.row.col.f32.f16.f16.f32 "
    "{%0,%1,%2,%3}, {%4,%5,%6,%7}, {%8,%9}, {%0,%1,%2,%3};"
    : "+f"(d[0]),"+f"(d[1]),"+f"(d[2]),"+f"(d[3])
    : "r"(a0),"r"(a1),"r"(a2),"r"(a3), "r"(b.x),"r"(b.y));
}

// group barrier arrival (counter self-resets; gen monotonic)
__device__ __forceinline__ void arrive(unsigned* ctr, unsigned* gen, unsigned target){
  __syncthreads();
  if (threadIdx.x == 0){
    __threadfence();
    unsigned old = atomicAdd(ctr, 1u);
    if (old == target - 1u){
      *(volatile unsigned*)ctr = 0u;
      __threadfence();
      atomicAdd(gen, 1u);
    }
  }
}

// straight-copy chunk staging: 128 rows x 64 halves, coalesced, conflict-free
__device__ __forceinline__ void stage_chunk(const __half* src, __half* dst, int tid){
  const int seg = tid & 7, r0 = tid >> 3;
  #pragma unroll
  for (int i = 0; i < 4; i++){
    int r = r0 + i*32;
    uint4 v = __ldcg((const uint4*)(src + r*HH + seg*8));
    *(uint4*)(dst + r*KP + seg*8) = v;
  }
}

__global__ void __launch_bounds__(NTHR, 1) stacklstm_h16(
    const float* __restrict__ x,   const int* __restrict__ ops,
    const float* __restrict__ Wih, const float* __restrict__ Whh,
    const float* __restrict__ bih, const float* __restrict__ bhh,
    float* __restrict__ out)
{
  extern __shared__ __align__(16) char smc[];
  uint2*  wfrag = (uint2*)(smc + OF_W);            // [nt*1024 + ktg*32 + lane]
  __half* abuf  = (__half*)(smc + OF_A);

  const int tid = threadIdx.x, bid = blockIdx.x;
  const int wr = tid >> 5, lane = tid & 31;
  const int layer = bid >> 6;
  const int j0 = (bid & 63) * 4;

  const float* Wi = Wih + layer*G4H*HH;
  const float* Wh = Whh + layer*G4H*HH;

  // ---- W fragment pack (once): fp16 pairs (k,k+1) and (k+8,k+9) ----
  for (int idx = tid; idx < 2048; idx += NTHR){
    int ln = idx & 31;
    int ktg = (idx >> 5) & 31;
    int nt = idx >> 10;
    int n  = nt*8 + (ln >> 2);
    int wrow = (n >> 2)*HH + j0 + (n & 3);
    int k0 = ktg*16 + (ln & 3)*2;
    const float* sw = (ktg < 16) ? (Wi + wrow*HH + k0) : (Wh + wrow*HH + k0 - HH);
    __half2 p0 = __halves2half2(__float2half_rn(__ldg(sw)),   __float2half_rn(__ldg(sw+1)));
    __half2 p1 = __halves2half2(__float2half_rn(__ldg(sw+8)), __float2half_rn(__ldg(sw+9)));
    wfrag[idx] = make_uint2(*(u32*)&p0, *(u32*)&p1);
  }

  // per-thread EW constants (identical to R6)
  const int q  = lane & 3;
  const int jj = (q >> 1) | ((q & 1) << 1);
  const int b1 = wr*16 + (lane >> 2);
  float biasv[4];
  #pragma unroll
  for (int g = 0; g < 4; g++){
    int wrow = g*HH + j0 + jj;
    biasv[g] = __ldg(bih + layer*G4H + wrow) + __ldg(bhh + layer*G4H + wrow);
  }

  // ---- x -> fp16 scratch (once, coalesced) ----
  {
    __half* xh = (__half*)g_xhB;
    #pragma unroll 1
    for (int i = 0; i < 8; i++){
      int gi = i*(NBLK*NTHR) + bid*NTHR + tid;   // uint4 index
      const float* sp = x + gi*8;
      float4 u = __ldg((const float4*)sp);
      float4 v = __ldg((const float4*)(sp+4));
      __half2 h0 = __halves2half2(__float2half_rn(u.x), __float2half_rn(u.y));
      __half2 h1 = __halves2half2(__float2half_rn(u.z), __float2half_rn(u.w));
      __half2 h2 = __halves2half2(__float2half_rn(v.x), __float2half_rn(v.y));
      __half2 h3 = __halves2half2(__float2half_rn(v.z), __float2half_rn(v.w));
      g_xhB[gi] = make_uint4(*(u32*)&h0, *(u32*)&h1, *(u32*)&h2, *(u32*)&h3);
    }
  }
  // zero parity-0 h states
  { int idx = bid*NTHR + tid;
    if (idx < BB*HH/8){
      g_h0sB[0][idx] = make_uint4(0,0,0,0);
      g_h1sB[0][idx] = make_uint4(0,0,0,0);
    } }

  unsigned base0 = 0, base1 = 0;
  if (tid == 0){
    base0 = *(volatile unsigned*)&g_gen0;
    base1 = *(volatile unsigned*)&g_gen1;
  }
  arrive(&g_ctr0, &g_gen0, 128u);   // init round: ALL 128 blocks

  float c0 = 0.f, c1 = 0.f, hk0 = 0.f, hk1 = 0.f;

  for (int t = 0; t < TT; t++){
    const __half* Alo = layer ? (const __half*)g_h0nB[t&1]
                              : ((const __half*)g_xhB) + t*BB*HH;
    const __half* Ahi = layer ? (const __half*)g_h1sB[t&1]
                              : (const __half*)g_h0sB[t&1];

    if (layer == 0){
      if (t > 0) stage_chunk(Alo, abuf, tid);    // x side: no dependency
      if (tid == 0){
        while (*(volatile unsigned*)&g_gen0 - base0 < (unsigned)(t+1)) __nanosleep(30);
        if (t >= 2)
          while (*(volatile unsigned*)&g_gen1 - base1 < (unsigned)(t-1)) __nanosleep(30);
        __threadfence();
      }
      __syncthreads();
      if (t == 0){ stage_chunk(Alo, abuf, tid); __syncthreads(); }
    } else {
      if (tid == 0){
        while (*(volatile unsigned*)&g_gen0 - base0 < (unsigned)(t+2)) __nanosleep(30);
        if (t >= 1)
          while (*(volatile unsigned*)&g_gen1 - base1 < (unsigned)(t)) __nanosleep(30);
        __threadfence();
      }
      __syncthreads();
      stage_chunk(Alo, abuf, tid);
      __syncthreads();
    }

    // ---- GEMM: D[128x16] = A[128x512] @ W^T, 8 chunks of 64 k ----
    float a0a[4]={0,0,0,0}, a0b[4]={0,0,0,0};   // nt0, even/odd ktl chains
    float a1a[4]={0,0,0,0}, a1b[4]={0,0,0,0};   // nt1
    #pragma unroll 1
    for (int ch = 0; ch < 8; ch++){
      uint4 nv[4];
      if (ch < 7){
        int nc = ch + 1;
        const __half* src = (nc < 4) ? Alo : Ahi;
        int ko = (nc & 3) * 64;
        const int seg = tid & 7, r0 = tid >> 3;
        #pragma unroll
        for (int i = 0; i < 4; i++){
          int r = r0 + i*32;
          nv[i] = __ldcg((const uint4*)(src + r*HH + ko + seg*8));
        }
      }
      const __half* ab = abuf + (ch & 1)*(128*KP);
      const __half* arow = ab + (wr*16 + (lane>>2))*KP + (lane&3)*2;
      #pragma unroll
      for (int ktl = 0; ktl < 4; ktl++){
        int ktg = ch*4 + ktl;
        u32 fa0 = *(const u32*)(arow + ktl*16);
        u32 fa1 = *(const u32*)(arow + ktl*16 + 8*KP);
        u32 fa2 = *(const u32*)(arow + ktl*16 + 8);
        u32 fa3 = *(const u32*)(arow + ktl*16 + 8*KP + 8);
        uint2 b0 = wfrag[ktg*32 + lane];
        uint2 b1 = wfrag[1024 + ktg*32 + lane];
        if (ktl & 1){ hmma(a0b, fa0,fa1,fa2,fa3, b0); hmma(a1b, fa0,fa1,fa2,fa3, b1); }
        else        { hmma(a0a, fa0,fa1,fa2,fa3, b0); hmma(a1a, fa0,fa1,fa2,fa3, b1); }
      }
      if (ch < 7){
        __half* bufn = abuf + ((ch+1) & 1)*(128*KP);
        const int seg = tid & 7, r0 = tid >> 3;
        #pragma unroll
        for (int i = 0; i < 4; i++){
          int r = r0 + i*32;
          *(uint4*)(bufn + r*KP + seg*8) = nv[i];
        }
      }
      __syncthreads();
    }
    float acc0[4], acc1[4];
    #pragma unroll
    for (int i = 0; i < 4; i++){ acc0[i] = a0a[i]+a0b[i]; acc1[i] = a1a[i]+a1b[i]; }

    // ---- in-register gate exchange + LSTM elementwise (identical to R6) ----
    {
      float s0 = __shfl_xor_sync(0xffffffffu, (q < 2) ? acc0[1] : acc0[0], 2);
      float s1 = __shfl_xor_sync(0xffffffffu, (q < 2) ? acc0[3] : acc0[2], 2);
      float s2 = __shfl_xor_sync(0xffffffffu, (q < 2) ? acc1[1] : acc1[0], 2);
      float s3 = __shfl_xor_sync(0xffffffffu, (q < 2) ? acc1[3] : acc1[2], 2);
      float gi0, gf0, gg0, go0, gi1, gf1, gg1, go1;
      if (q < 2){
        gi0 = acc0[0]; gf0 = s0; gg0 = acc1[0]; go0 = s2;
        gi1 = acc0[2]; gf1 = s1; gg1 = acc1[2]; go1 = s3;
      } else {
        gi0 = s0; gf0 = acc0[1]; gg0 = s2; go0 = acc1[1];
        gi1 = s1; gf1 = acc0[3]; gg1 = s3; go1 = acc1[3];
      }
      gi0 += biasv[0]; gf0 += biasv[1]; gg0 += biasv[2]; go0 += biasv[3];
      gi1 += biasv[0]; gf1 += biasv[1]; gg1 += biasv[2]; go1 += biasv[3];

      const int op0 = __ldg(ops + t*BB + b1);
      const int op1 = __ldg(ops + t*BB + b1 + 8);
      float cn0 = sigf(gf0)*c0 + sigf(gi0)*tanhf(gg0);
      float hn0 = sigf(go0)*tanhf(cn0);
      float cn1 = sigf(gf1)*c1 + sigf(gi1)*tanhf(gg1);
      float hn1 = sigf(go1)*tanhf(cn1);
      if (op0){ c0 = cn0; hk0 = hn0; }
      if (op1){ c1 = cn1; hk1 = hn1; }

      const int o0 = b1*HH + j0 + jj;
      const int o1 = o0 + 8*HH;
      if (layer == 0){
        __half* fresh = (__half*)g_h0nB[t&1];
        __half* keep  = (__half*)g_h0sB[(t+1)&1];
        fresh[o0] = __float2half_rn(hn0); fresh[o1] = __float2half_rn(hn1);
        keep[o0]  = __float2half_rn(hk0); keep[o1]  = __float2half_rn(hk1);
      } else {
        float* fresh = out + t*BB*HH;
        __half* keep = (__half*)g_h1sB[(t+1)&1];
        fresh[o0] = hn0; fresh[o1] = hn1;
        keep[o0]  = __float2half_rn(hk0); keep[o1]  = __float2half_rn(hk1);
      }
    }

    if (layer == 0) arrive(&g_ctr0, &g_gen0, 64u);
    else            arrive(&g_ctr1, &g_gen1, 64u);
  }
}

extern "C" void kernel_launch(void* const* d_in, const int* in_sizes, int n_in,
                              void* d_out, int out_size)
{
  const float* x   = (const float*)d_in[0];
  const int*   ops = (const int*)  d_in[1];
  const float* Wih = (const float*)d_in[2];
  const float* Whh = (const float*)d_in[3];
  const float* bih = (const float*)d_in[4];
  const float* bhh = (const float*)d_in[5];
  float* out = (float*)d_out;
  static int inited = 0;
  if (!inited){
    cudaFuncSetAttribute(stacklstm_h16, cudaFuncAttributeMaxDynamicSharedMemorySize, SM_BYTES);
    inited = 1;
  }
  stacklstm_h16<<<NBLK, NTHR, SM_BYTES>>>(x, ops, Wih, Whh, bih, bhh, out);
}

// round 10
// speedup vs baseline: 3.6546x; 1.0701x over previous
#include <cuda_runtime.h>
#include <cuda_fp16.h>
#include <cstdint>
typedef uint32_t u32;

#define TT 64
#define BB 128
#define HH 256
#define G4H 1024
#define NBLK 128
#define NTHR 256
#define ASTR 520         /* halves per A row: 512 + 8 pad */

// dynamic smem layout (bytes)
#define OF_W 0                       /* W frags: [nt2][kt32][lane32] uint2 = 16 KB */
#define OF_A 16384                   /* A: 128 rows x ASTR halves = 130 KB         */
#define SM_BYTES (16384 + 128*ASTR*2)

// persistent state (16B-aligned for LDG.128)
__device__ uint4 g_h0sB[2][BB*HH/8];
__device__ uint4 g_h1sB[2][BB*HH/8];
__device__ uint4 g_h0nB[2][BB*HH/8];
__device__ uint4 g_xhB[TT*BB*HH/8];   // fp16 copy of x
__device__ unsigned g_ctr0, g_gen0;   // layer0 group (init round is 128-wide)
__device__ unsigned g_ctr1, g_gen1;   // layer1 group

__device__ __forceinline__ float sigf(float v){ return 1.0f/(1.0f+__expf(-v)); }

// m16n8k16 fp16 mma, fp32 accum
__device__ __forceinline__ void hmma(float* d, u32 a0, u32 a1, u32 a2, u32 a3, uint2 b){
  asm volatile("mma.sync.aligned.m16n8k16.row.col.f32.f16.f16.f32 "
    "{%0,%1,%2,%3}, {%4,%5,%6,%7}, {%8,%9}, {%0,%1,%2,%3};"
    : "+f"(d[0]),"+f"(d[1]),"+f"(d[2]),"+f"(d[3])
    : "r"(a0),"r"(a1),"r"(a2),"r"(a3), "r"(b.x),"r"(b.y));
}

// group barrier arrival (counter self-resets; gen monotonic)
__device__ __forceinline__ void arrive(unsigned* ctr, unsigned* gen, unsigned target){
  __syncthreads();
  if (threadIdx.x == 0){
    __threadfence();
    unsigned old = atomicAdd(ctr, 1u);
    if (old == target - 1u){
      *(volatile unsigned*)ctr = 0u;
      __threadfence();
      atomicAdd(gen, 1u);
    }
  }
}
__device__ __forceinline__ void waitgen(volatile unsigned* gen, unsigned base, unsigned v){
  while (*gen - base < v){ }
}

// stage one 256-half K-half: 16 coalesced LDG.128 -> smem rows (off = 0 or 256)
__device__ __forceinline__ void stage_half(const __half* src, __half* abuf, int off, int tid){
  const int seg = tid & 31, rw = tid >> 5;
  #pragma unroll
  for (int i = 0; i < 16; i++){
    int r = rw + i*8;
    uint4 v = __ldcg((const uint4*)(src + r*HH + seg*8));
    *(uint4*)(abuf + r*ASTR + off + seg*8) = v;
  }
}

// compute one K-half = 16 k-tiles into 4 accumulator chains
__device__ __forceinline__ void compute_half(
    const __half* arow, const uint2* wfrag, int kbase,
    float* a0a, float* a0b, float* a1a, float* a1b)
{
  #pragma unroll
  for (int ktl = 0; ktl < 16; ktl++){
    int kt = kbase + ktl;
    u32 fa0 = *(const u32*)(arow + kt*16);
    u32 fa1 = *(const u32*)(arow + kt*16 + 8*ASTR);
    u32 fa2 = *(const u32*)(arow + kt*16 + 8);
    u32 fa3 = *(const u32*)(arow + kt*16 + 8*ASTR + 8);
    uint2 b0 = wfrag[kt*32 + (threadIdx.x & 31)];
    uint2 b1 = wfrag[1024 + kt*32 + (threadIdx.x & 31)];
    if (ktl & 1){ hmma(a0b, fa0,fa1,fa2,fa3, b0); hmma(a1b, fa0,fa1,fa2,fa3, b1); }
    else        { hmma(a0a, fa0,fa1,fa2,fa3, b0); hmma(a1a, fa0,fa1,fa2,fa3, b1); }
  }
}

__global__ void __launch_bounds__(NTHR, 1) stacklstm_h16(
    const float* __restrict__ x,   const int* __restrict__ ops,
    const float* __restrict__ Wih, const float* __restrict__ Whh,
    const float* __restrict__ bih, const float* __restrict__ bhh,
    float* __restrict__ out)
{
  extern __shared__ __align__(16) char smc[];
  uint2*  wfrag = (uint2*)(smc + OF_W);            // [nt*1024 + kt*32 + lane]
  __half* abuf  = (__half*)(smc + OF_A);

  const int tid = threadIdx.x, bid = blockIdx.x;
  const int wr = tid >> 5, lane = tid & 31;
  const int layer = bid >> 6;
  const int j0 = (bid & 63) * 4;

  const float* Wi = Wih + layer*G4H*HH;
  const float* Wh = Whh + layer*G4H*HH;

  // ---- W fragment pack (once): [nt2][kt32][lane32] ----
  for (int idx = tid; idx < 2048; idx += NTHR){
    int ln = idx & 31;
    int kt = (idx >> 5) & 31;
    int nt = idx >> 10;
    int n  = nt*8 + (ln >> 2);
    int wrow = (n >> 2)*HH + j0 + (n & 3);
    int k0 = kt*16 + (ln & 3)*2;
    const float* sw = (kt < 16) ? (Wi + wrow*HH + k0) : (Wh + wrow*HH + k0 - HH);
    __half2 p0 = __halves2half2(__float2half_rn(__ldg(sw)),   __float2half_rn(__ldg(sw+1)));
    __half2 p1 = __halves2half2(__float2half_rn(__ldg(sw+8)), __float2half_rn(__ldg(sw+9)));
    wfrag[idx] = make_uint2(*(u32*)&p0, *(u32*)&p1);
  }

  // per-thread EW constants
  const int q  = lane & 3;
  const int jj = (q >> 1) | ((q & 1) << 1);
  const int b1 = wr*16 + (lane >> 2);
  float biasv[4];
  #pragma unroll
  for (int g = 0; g < 4; g++){
    int wrow = g*HH + j0 + jj;
    biasv[g] = __ldg(bih + layer*G4H + wrow) + __ldg(bhh + layer*G4H + wrow);
  }

  // ---- x -> fp16 scratch (once, coalesced) ----
  #pragma unroll 1
  for (int i = 0; i < 8; i++){
    int gi = i*(NBLK*NTHR) + bid*NTHR + tid;
    const float* sp = x + gi*8;
    float4 u = __ldg((const float4*)sp);
    float4 v = __ldg((const float4*)(sp+4));
    __half2 h0 = __halves2half2(__float2half_rn(u.x), __float2half_rn(u.y));
    __half2 h1 = __halves2half2(__float2half_rn(u.z), __float2half_rn(u.w));
    __half2 h2 = __halves2half2(__float2half_rn(v.x), __float2half_rn(v.y));
    __half2 h3 = __halves2half2(__float2half_rn(v.z), __float2half_rn(v.w));
    g_xhB[gi] = make_uint4(*(u32*)&h0, *(u32*)&h1, *(u32*)&h2, *(u32*)&h3);
  }
  // zero parity-0 h states
  { int idx = bid*NTHR + tid;
    if (idx < BB*HH/8){
      g_h0sB[0][idx] = make_uint4(0,0,0,0);
      g_h1sB[0][idx] = make_uint4(0,0,0,0);
    } }

  unsigned base0 = 0, base1 = 0;
  if (tid == 0){
    base0 = *(volatile unsigned*)&g_gen0;
    base1 = *(volatile unsigned*)&g_gen1;
  }
  arrive(&g_ctr0, &g_gen0, 128u);   // init round: ALL 128 blocks

  float c0 = 0.f, c1 = 0.f, hk0 = 0.f, hk1 = 0.f;
  const __half* arow = abuf + (wr*16 + (lane>>2))*ASTR + (lane&3)*2;

  for (int t = 0; t < TT; t++){
    const __half* Alo = layer ? (const __half*)g_h0nB[t&1]
                              : ((const __half*)g_xhB) + t*BB*HH;
    const __half* Ahi = layer ? (const __half*)g_h1sB[t&1]
                              : (const __half*)g_h0sB[t&1];

    float a0a[4]={0,0,0,0}, a0b[4]={0,0,0,0};
    float a1a[4]={0,0,0,0}, a1b[4]={0,0,0,0};

    if (layer == 0){
      // lo = x: ready now. Stage + compute BEFORE any wait.
      stage_half(Alo, abuf, 0, tid);
      __syncthreads();
      compute_half(arow, wfrag, 0, a0a, a0b, a1a, a1b);
      // wait: own group finished phase t-1 (h0s ready) + layer1 finished t-2
      // (h0n parity buffer free for EW overwrite)
      if (tid == 0){
        waitgen(&g_gen0, base0, (unsigned)(t+1));
        if (t >= 2) waitgen(&g_gen1, base1, (unsigned)(t-1));
        __threadfence();
      }
      __syncthreads();
      stage_half(Ahi, abuf, 256, tid);
      __syncthreads();
      compute_half(arow, wfrag, 16, a0a, a0b, a1a, a1b);
    } else {
      // hi = h1s: needs only own group phase t-1. Do it first.
      if (tid == 0){
        if (t >= 1) waitgen(&g_gen1, base1, (unsigned)t);
        __threadfence();
      }
      __syncthreads();
      stage_half(Ahi, abuf, 256, tid);
      __syncthreads();
      compute_half(arow, wfrag, 16, a0a, a0b, a1a, a1b);
      // lo = h0n(t): needs all layer0 finished phase t
      if (tid == 0){
        waitgen(&g_gen0, base0, (unsigned)(t+2));
        __threadfence();
      }
      __syncthreads();
      stage_half(Alo, abuf, 0, tid);
      __syncthreads();
      compute_half(arow, wfrag, 0, a0a, a0b, a1a, a1b);
    }

    float acc0[4], acc1[4];
    #pragma unroll
    for (int i = 0; i < 4; i++){ acc0[i] = a0a[i]+a0b[i]; acc1[i] = a1a[i]+a1b[i]; }

    // ---- in-register gate exchange + LSTM elementwise ----
    {
      float s0 = __shfl_xor_sync(0xffffffffu, (q < 2) ? acc0[1] : acc0[0], 2);
      float s1 = __shfl_xor_sync(0xffffffffu, (q < 2) ? acc0[3] : acc0[2], 2);
      float s2 = __shfl_xor_sync(0xffffffffu, (q < 2) ? acc1[1] : acc1[0], 2);
      float s3 = __shfl_xor_sync(0xffffffffu, (q < 2) ? acc1[3] : acc1[2], 2);
      float gi0, gf0, gg0, go0, gi1, gf1, gg1, go1;
      if (q < 2){
        gi0 = acc0[0]; gf0 = s0; gg0 = acc1[0]; go0 = s2;
        gi1 = acc0[2]; gf1 = s1; gg1 = acc1[2]; go1 = s3;
      } else {
        gi0 = s0; gf0 = acc0[1]; gg0 = s2; go0 = acc1[1];
        gi1 = s1; gf1 = acc0[3]; gg1 = s3; go1 = acc1[3];
      }
      gi0 += biasv[0]; gf0 += biasv[1]; gg0 += biasv[2]; go0 += biasv[3];
      gi1 += biasv[0]; gf1 += biasv[1]; gg1 += biasv[2]; go1 += biasv[3];

      const int op0 = __ldg(ops + t*BB + b1);
      const int op1 = __ldg(ops + t*BB + b1 + 8);
      float cn0 = sigf(gf0)*c0 + sigf(gi0)*tanhf(gg0);
      float hn0 = sigf(go0)*tanhf(cn0);
      float cn1 = sigf(gf1)*c1 + sigf(gi1)*tanhf(gg1);
      float hn1 = sigf(go1)*tanhf(cn1);
      if (op0){ c0 = cn0; hk0 = hn0; }
      if (op1){ c1 = cn1; hk1 = hn1; }

      const int o0 = b1*HH + j0 + jj;
      const int o1 = o0 + 8*HH;
      if (layer == 0){
        __half* fresh = (__half*)g_h0nB[t&1];
        __half* keep  = (__half*)g_h0sB[(t+1)&1];
        fresh[o0] = __float2half_rn(hn0); fresh[o1] = __float2half_rn(hn1);
        keep[o0]  = __float2half_rn(hk0); keep[o1]  = __float2half_rn(hk1);
      } else {
        float* fresh = out + t*BB*HH;
        __half* keep = (__half*)g_h1sB[(t+1)&1];
        fresh[o0] = hn0; fresh[o1] = hn1;
        keep[o0]  = __float2half_rn(hk0); keep[o1]  = __float2half_rn(hk1);
      }
    }

    if (layer == 0) arrive(&g_ctr0, &g_gen0, 64u);
    else            arrive(&g_ctr1, &g_gen1, 64u);
  }
}

extern "C" void kernel_launch(void* const* d_in, const int* in_sizes, int n_in,
                              void* d_out, int out_size)
{
  const float* x   = (const float*)d_in[0];
  const int*   ops = (const int*)  d_in[1];
  const float* Wih = (const float*)d_in[2];
  const float* Whh = (const float*)d_in[3];
  const float* bih = (const float*)d_in[4];
  const float* bhh = (const float*)d_in[5];
  float* out = (float*)d_out;
  // unconditional (idempotent, capture-safe): no static call-count guards
  cudaFuncSetAttribute(stacklstm_h16, cudaFuncAttributeMaxDynamicSharedMemorySize, SM_BYTES);
  stacklstm_h16<<<NBLK, NTHR, SM_BYTES>>>(x, ops, Wih, Whh, bih, bhh, out);
}

// round 12
// speedup vs baseline: 4.4065x; 1.2057x over previous
#include <cuda_runtime.h>
#include <cuda_fp16.h>
#include <cstdint>
typedef uint32_t u32;

#define TT 64
#define BB 128
#define HH 256
#define G4H 1024
#define NBLK 128
#define NTHR 256

// fragment-major state arrays: unit (kt,row) = 32B, half order within unit:
// [k(2q),k(2q+1),k(2q+8),k(2q+9)] for q=0..3.  kt = j>>4 (16 kt per 256 k).
__device__ uint4 g_xF4[TT*16*BB*2];      // x, converted+permuted once (4 MB)
__device__ uint4 g_h0nF4[2][16*BB*2];    // fresh layer0 hidden (layer1 input)
__device__ uint4 g_h0sF4[2][16*BB*2];    // layer0 carried state
__device__ uint4 g_h1sF4[2][16*BB*2];    // layer1 carried state
__device__ unsigned g_ctr0, g_gen0;      // layer0 group (init round 128-wide)
__device__ unsigned g_ctr1, g_gen1;      // layer1 group

__device__ __forceinline__ float sigf(float v){ return 1.0f/(1.0f+__expf(-v)); }

// m16n8k16 fp16 mma, fp32 accum
__device__ __forceinline__ void hmma(float* d, u32 a0, u32 a1, u32 a2, u32 a3, uint2 b){
  asm volatile("mma.sync.aligned.m16n8k16.row.col.f32.f16.f16.f32 "
    "{%0,%1,%2,%3}, {%4,%5,%6,%7}, {%8,%9}, {%0,%1,%2,%3};"
    : "+f"(d[0]),"+f"(d[1]),"+f"(d[2]),"+f"(d[3])
    : "r"(a0),"r"(a1),"r"(a2),"r"(a3), "r"(b.x),"r"(b.y));
}

__device__ __forceinline__ void arrive(unsigned* ctr, unsigned* gen, unsigned target){
  __syncthreads();
  if (threadIdx.x == 0){
    __threadfence();
    unsigned old = atomicAdd(ctr, 1u);
    if (old == target - 1u){
      *(volatile unsigned*)ctr = 0u;
      __threadfence();
      atomicAdd(gen, 1u);
    }
  }
}
__device__ __forceinline__ void waitgen(volatile unsigned* gen, unsigned base, unsigned v){
  while (*gen - base < v){ }
}

// half-position of INTRA-TILE k-index i (0..15 ONLY) inside a 32B unit
__device__ __forceinline__ int fragoff(int i){
  return ((i & 7) >> 1)*4 + ((i >> 3) << 1) + (i & 1);
}

// one K-half (16 k-tiles) straight from fragment-major global memory.
// Per kt per lane: 2 LDG.64 (rows b1, b1+8) — warp-coalesced 2x256B.
__device__ __forceinline__ void compute_frag(
    const uint2* __restrict__ F, const uint2* __restrict__ wfrag,
    int kbase, int b1q, int b2q, int lane,
    float* a0a, float* a0b, float* a1a, float* a1b)
{
  #pragma unroll
  for (int ktl = 0; ktl < 16; ktl++){
    uint2 va = __ldcg(F + ktl*512 + b1q);   // {a0 = (b1, k-lo), a2 = (b1, k-hi)}
    uint2 vb = __ldcg(F + ktl*512 + b2q);   // {a1, a3} for row b1+8
    uint2 w0 = wfrag[(kbase+ktl)*32 + lane];
    uint2 w1 = wfrag[1024 + (kbase+ktl)*32 + lane];
    if (ktl & 1){ hmma(a0b, va.x, vb.x, va.y, vb.y, w0); hmma(a1b, va.x, vb.x, va.y, vb.y, w1); }
    else        { hmma(a0a, va.x, vb.x, va.y, vb.y, w0); hmma(a1a, va.x, vb.x, va.y, vb.y, w1); }
  }
}

__global__ void __launch_bounds__(NTHR, 1) stacklstm_h16(
    const float* __restrict__ x,   const int* __restrict__ ops,
    const float* __restrict__ Wih, const float* __restrict__ Whh,
    const float* __restrict__ bih, const float* __restrict__ bhh,
    float* __restrict__ out)
{
  __shared__ uint2 wfrag[2048];     // [nt*1024 + kt*32 + lane], 16 KB

  const int tid = threadIdx.x, bid = blockIdx.x;
  const int wr = tid >> 5, lane = tid & 31;
  const int layer = bid >> 6;
  const int j0 = (bid & 63) * 4;

  const float* Wi = Wih + layer*G4H*HH;
  const float* Wh = Whh + layer*G4H*HH;

  // ---- W fragment pack (once): [nt2][kt32][lane32] ----
  for (int idx = tid; idx < 2048; idx += NTHR){
    int ln = idx & 31;
    int kt = (idx >> 5) & 31;
    int nt = idx >> 10;
    int n  = nt*8 + (ln >> 2);
    int wrow = (n >> 2)*HH + j0 + (n & 3);
    int k0 = kt*16 + (ln & 3)*2;
    const float* sw = (kt < 16) ? (Wi + wrow*HH + k0) : (Wh + wrow*HH + k0 - HH);
    __half2 p0 = __halves2half2(__float2half_rn(__ldg(sw)),   __float2half_rn(__ldg(sw+1)));
    __half2 p1 = __halves2half2(__float2half_rn(__ldg(sw+8)), __float2half_rn(__ldg(sw+9)));
    wfrag[idx] = make_uint2(*(u32*)&p0, *(u32*)&p1);
  }

  // per-thread EW constants
  const int q  = lane & 3;
  const int jj = (q >> 1) | ((q & 1) << 1);
  const int b1 = wr*16 + (lane >> 2);
  float biasv[4];
  #pragma unroll
  for (int g = 0; g < 4; g++){
    int wrow = g*HH + j0 + jj;
    biasv[g] = __ldg(bih + layer*G4H + wrow) + __ldg(bhh + layer*G4H + wrow);
  }

  // ---- x -> fragment-major fp16 (once): unit u = (t, kt, row) ----
  #pragma unroll 1
  for (int u0 = 0; u0 < 4; u0++){
    int u = u0*(NBLK*NTHR) + bid*NTHR + tid;   // 0..131071
    int t   = u >> 11;
    int kt  = (u >> 7) & 15;
    int row = u & 127;
    const float* sp = x + (t*BB + row)*HH + kt*16;
    float4 f0 = __ldg((const float4*)sp);
    float4 f1 = __ldg((const float4*)(sp+4));
    float4 f2 = __ldg((const float4*)(sp+8));
    float4 f3 = __ldg((const float4*)(sp+12));
    __half2 d0 = __halves2half2(__float2half_rn(f0.x), __float2half_rn(f0.y));  // k0,k1
    __half2 d1 = __halves2half2(__float2half_rn(f2.x), __float2half_rn(f2.y));  // k8,k9
    __half2 d2 = __halves2half2(__float2half_rn(f0.z), __float2half_rn(f0.w));  // k2,k3
    __half2 d3 = __halves2half2(__float2half_rn(f2.z), __float2half_rn(f2.w));  // k10,k11
    __half2 d4 = __halves2half2(__float2half_rn(f1.x), __float2half_rn(f1.y));  // k4,k5
    __half2 d5 = __halves2half2(__float2half_rn(f3.x), __float2half_rn(f3.y));  // k12,k13
    __half2 d6 = __halves2half2(__float2half_rn(f1.z), __float2half_rn(f1.w));  // k6,k7
    __half2 d7 = __halves2half2(__float2half_rn(f3.z), __float2half_rn(f3.w));  // k14,k15
    uint4* dst = g_xF4 + (size_t)((t*16 + kt)*128 + row)*2;
    dst[0] = make_uint4(*(u32*)&d0, *(u32*)&d1, *(u32*)&d2, *(u32*)&d3);
    dst[1] = make_uint4(*(u32*)&d4, *(u32*)&d5, *(u32*)&d6, *(u32*)&d7);
  }
  // zero parity-0 state frags
  { int idx = bid*NTHR + tid;
    if (idx < 16*BB*2){
      g_h0sF4[0][idx] = make_uint4(0,0,0,0);
      g_h1sF4[0][idx] = make_uint4(0,0,0,0);
    } }

  unsigned base0 = 0, base1 = 0;
  if (tid == 0){
    base0 = *(volatile unsigned*)&g_gen0;
    base1 = *(volatile unsigned*)&g_gen1;
  }
  arrive(&g_ctr0, &g_gen0, 128u);   // init round: ALL 128 blocks
  // ALL blocks wait for init completion before touching any shared data
  // (x frags + zeroed states globally visible from here on).
  if (tid == 0){ waitgen(&g_gen0, base0, 1u); __threadfence(); }
  __syncthreads();

  float c0 = 0.f, c1 = 0.f, hk0 = 0.f, hk1 = 0.f;
  const int b1q = b1*4 + q, b2q = (b1+8)*4 + q;
  const int ktv = j0 >> 4;                        // kt of this block's j-slice
  const int fo  = fragoff((j0 + jj) & 15);        // INTRA-TILE offset (bug fix)

  for (int t = 0; t < TT; t++){
    float a0a[4]={0,0,0,0}, a0b[4]={0,0,0,0};
    float a1a[4]={0,0,0,0}, a1b[4]={0,0,0,0};

    if (layer == 0){
      // lo = x frags: ready now, compute BEFORE any wait
      compute_frag((const uint2*)(g_xF4 + (size_t)t*16*128*2), wfrag, 0,
                   b1q, b2q, lane, a0a, a0b, a1a, a1b);
      // wait: own group done t-1 (h0s ready) + layer1 done t-2 (h0n buf free)
      if (tid == 0){
        waitgen(&g_gen0, base0, (unsigned)(t+1));
        if (t >= 2) waitgen(&g_gen1, base1, (unsigned)(t-1));
        __threadfence();
      }
      __syncthreads();
      compute_frag((const uint2*)g_h0sF4[t&1], wfrag, 16,
                   b1q, b2q, lane, a0a, a0b, a1a, a1b);
    } else {
      // hi = h1s: needs only own group done t-1
      if (tid == 0){
        if (t >= 1) waitgen(&g_gen1, base1, (unsigned)t);
        __threadfence();
      }
      __syncthreads();
      compute_frag((const uint2*)g_h1sF4[t&1], wfrag, 16,
                   b1q, b2q, lane, a0a, a0b, a1a, a1b);
      // lo = h0n(t): needs all layer0 done phase t
      if (tid == 0){
        waitgen(&g_gen0, base0, (unsigned)(t+2));
        __threadfence();
      }
      __syncthreads();
      compute_frag((const uint2*)g_h0nF4[t&1], wfrag, 0,
                   b1q, b2q, lane, a0a, a0b, a1a, a1b);
    }

    float acc0[4], acc1[4];
    #pragma unroll
    for (int i = 0; i < 4; i++){ acc0[i] = a0a[i]+a0b[i]; acc1[i] = a1a[i]+a1b[i]; }

    // ---- in-register gate exchange + LSTM elementwise ----
    {
      float s0 = __shfl_xor_sync(0xffffffffu, (q < 2) ? acc0[1] : acc0[0], 2);
      float s1 = __shfl_xor_sync(0xffffffffu, (q < 2) ? acc0[3] : acc0[2], 2);
      float s2 = __shfl_xor_sync(0xffffffffu, (q < 2) ? acc1[1] : acc1[0], 2);
      float s3 = __shfl_xor_sync(0xffffffffu, (q < 2) ? acc1[3] : acc1[2], 2);
      float gi0, gf0, gg0, go0, gi1, gf1, gg1, go1;
      if (q < 2){
        gi0 = acc0[0]; gf0 = s0; gg0 = acc1[0]; go0 = s2;
        gi1 = acc0[2]; gf1 = s1; gg1 = acc1[2]; go1 = s3;
      } else {
        gi0 = s0; gf0 = acc0[1]; gg0 = s2; go0 = acc1[1];
        gi1 = s1; gf1 = acc0[3]; gg1 = s3; go1 = acc1[3];
      }
      gi0 += biasv[0]; gf0 += biasv[1]; gg0 += biasv[2]; go0 += biasv[3];
      gi1 += biasv[0]; gf1 += biasv[1]; gg1 += biasv[2]; go1 += biasv[3];

      const int op0 = __ldg(ops + t*BB + b1);
      const int op1 = __ldg(ops + t*BB + b1 + 8);
      float cn0 = sigf(gf0)*c0 + sigf(gi0)*tanhf(gg0);
      float hn0 = sigf(go0)*tanhf(cn0);
      float cn1 = sigf(gf1)*c1 + sigf(gi1)*tanhf(gg1);
      float hn1 = sigf(go1)*tanhf(cn1);
      if (op0){ c0 = cn0; hk0 = hn0; }
      if (op1){ c1 = cn1; hk1 = hn1; }

      const int u0h = (ktv*128 + b1)*16 + fo;        // frag half-offset row b1
      const int u1h = (ktv*128 + b1 + 8)*16 + fo;    // row b1+8
      if (layer == 0){
        __half* fresh = (__half*)g_h0nF4[t&1];
        __half* keep  = (__half*)g_h0sF4[(t+1)&1];
        fresh[u0h] = __float2half_rn(hn0); fresh[u1h] = __float2half_rn(hn1);
        keep[u0h]  = __float2half_rn(hk0); keep[u1h]  = __float2half_rn(hk1);
      } else {
        float* fresh = out + t*BB*HH;
        __half* keep = (__half*)g_h1sF4[(t+1)&1];
        fresh[b1*HH + j0 + jj]       = hn0;
        fresh[(b1+8)*HH + j0 + jj]   = hn1;
        keep[u0h]  = __float2half_rn(hk0); keep[u1h]  = __float2half_rn(hk1);
      }
    }

    if (layer == 0) arrive(&g_ctr0, &g_gen0, 64u);
    else            arrive(&g_ctr1, &g_gen1, 64u);
  }
}

extern "C" void kernel_launch(void* const* d_in, const int* in_sizes, int n_in,
                              void* d_out, int out_size)
{
  const float* x   = (const float*)d_in[0];
  const int*   ops = (const int*)  d_in[1];
  const float* Wih = (const float*)d_in[2];
  const float* Whh = (const float*)d_in[3];
  const float* bih = (const float*)d_in[4];
  const float* bhh = (const float*)d_in[5];
  float* out = (float*)d_out;
  stacklstm_h16<<<NBLK, NTHR>>>(x, ops, Wih, Whh, bih, bhh, out);
}

// round 13
// speedup vs baseline: 5.5892x; 1.2684x over previous
#include <cuda_runtime.h>
#include <cuda_fp16.h>
#include <cstdint>
typedef uint32_t u32;

#define TT 64
#define BB 128
#define HH 256
#define G4H 1024
#define NBLK 128
#define NTHR 256

// fragment-major state arrays: unit (kt,row) = 32B, half order within unit:
// [k(2q),k(2q+1),k(2q+8),k(2q+9)] for q=0..3.
__device__ uint4 g_xF4[TT*16*BB*2];      // x, converted+permuted once
__device__ uint4 g_h0nF4[2][16*BB*2];    // fresh layer0 hidden (layer1 input)
__device__ uint4 g_h0sF4[2][16*BB*2];    // layer0 carried state
__device__ uint4 g_h1sF4[2][16*BB*2];    // layer1 carried state
__device__ unsigned g_flags[NBLK*64];    // per-block step flag, 256B stride
__device__ unsigned g_ctr0, g_gen0;      // init barrier only (monotonic)

__device__ __forceinline__ float sigf(float v){ return 1.0f/(1.0f+__expf(-v)); }

__device__ __forceinline__ unsigned ldacq(const unsigned* p){
  unsigned v; asm volatile("ld.global.acquire.gpu.u32 %0, [%1];" : "=r"(v) : "l"(p) : "memory");
  return v;
}
__device__ __forceinline__ void strel(unsigned* p, unsigned v){
  asm volatile("st.global.release.gpu.u32 [%0], %1;" :: "l"(p), "r"(v) : "memory");
}

// m16n8k16 fp16 mma, fp32 accum
__device__ __forceinline__ void hmma(float* d, u32 a0, u32 a1, u32 a2, u32 a3, uint2 b){
  asm volatile("mma.sync.aligned.m16n8k16.row.col.f32.f16.f16.f32 "
    "{%0,%1,%2,%3}, {%4,%5,%6,%7}, {%8,%9}, {%0,%1,%2,%3};"
    : "+f"(d[0]),"+f"(d[1]),"+f"(d[2]),"+f"(d[3])
    : "r"(a0),"r"(a1),"r"(a2),"r"(a3), "r"(b.x),"r"(b.y));
}

// init-only central barrier (monotonic gen, replay-safe)
__device__ __forceinline__ void init_arrive_and_wait(unsigned base){
  __syncthreads();
  if (threadIdx.x == 0){
    __threadfence();
    unsigned old = atomicAdd(&g_ctr0, 1u);
    if (old == (unsigned)(NBLK-1)){
      *(volatile unsigned*)&g_ctr0 = 0u;
      __threadfence();
      atomicAdd(&g_gen0, 1u);
    }
    while (*(volatile unsigned*)&g_gen0 - base < 1u){ }
    __threadfence();
  }
  __syncthreads();
}

// warp 0 polls the 32 flags of group gbase until all >= tgt (callers sync after)
__device__ __forceinline__ void wait_flags(int gbase, unsigned tgt){
  if (threadIdx.x < 32){
    const unsigned* p = &g_flags[(gbase + threadIdx.x)*64];
    unsigned v = ldacq(p);
    while (!__all_sync(0xffffffffu, v >= tgt)) v = ldacq(p);
  }
}

// half-position of INTRA-TILE k-index i (0..15 ONLY) inside a 32B unit
__device__ __forceinline__ int fragoff(int i){
  return ((i & 7) >> 1)*4 + ((i >> 3) << 1) + (i & 1);
}

// one 256-k source (16 k-tiles) from fragment-major global; per kt per lane:
// 2 coalesced LDG.64. wf = this warp-col's fragment table; kbase selects W half.
__device__ __forceinline__ void compute_frag(
    const uint2* __restrict__ F, const uint2* __restrict__ wf,
    int kbase, int b1q, int b2q, int lane,
    float* a0a, float* a0b, float* a1a, float* a1b)
{
  #pragma unroll
  for (int ktl = 0; ktl < 16; ktl++){
    int kt = kbase + ktl;
    uint2 va = __ldcg(F + ktl*512 + b1q);
    uint2 vb = __ldcg(F + ktl*512 + b2q);
    uint2 w0 = wf[kt*32 + lane];
    uint2 w1 = wf[1024 + kt*32 + lane];
    if (ktl & 1){ hmma(a0b, va.x, vb.x, va.y, vb.y, w0); hmma(a1b, va.x, vb.x, va.y, vb.y, w1); }
    else        { hmma(a0a, va.x, vb.x, va.y, vb.y, w0); hmma(a1a, va.x, vb.x, va.y, vb.y, w1); }
  }
}

__global__ void __launch_bounds__(NTHR, 1) stacklstm_h16(
    const float* __restrict__ x,   const int* __restrict__ ops,
    const float* __restrict__ Wih, const float* __restrict__ Whh,
    const float* __restrict__ bih, const float* __restrict__ bhh,
    float* __restrict__ out)
{
  __shared__ uint2 wfrag[4096];     // [wc2][nt2][kt32][lane32], 32 KB

  const int tid = threadIdx.x, bid = blockIdx.x;
  const int wid = tid >> 5, lane = tid & 31;
  const int layer = bid >> 6;            // 0 / 1
  const int half  = (bid >> 5) & 1;      // batch half
  const int cg    = bid & 31;            // 8 j's per block
  const int j0    = cg * 8;
  const int b0    = half * 64;
  const int wr2   = wid >> 1;            // 4 row groups of 16
  const int wc    = wid & 1;             // 2 col sub-blocks of 4 j's

  const int own_g = bid & ~31;           // own flag-group base (block idx)
  const int l0_g  = own_g - 64;          // for layer1: matching layer0 group
  const int l1_g  = own_g + 64;          // for layer0: matching layer1 group

  const float* Wi = Wih + layer*G4H*HH;
  const float* Wh = Whh + layer*G4H*HH;

  // ---- W fragment pack (once): [wc2][nt2][kt32][lane32] ----
  for (int idx = tid; idx < 4096; idx += NTHR){
    int ln = idx & 31;
    int kt = (idx >> 5) & 31;
    int nt = (idx >> 10) & 1;
    int wc2 = idx >> 11;
    int n  = nt*8 + (ln >> 2);                       // sub-block col 0..15
    int wrow = (n >> 2)*HH + j0 + wc2*4 + (n & 3);   // gate = n>>2, jl = n&3
    int k0 = kt*16 + (ln & 3)*2;
    const float* sw = (kt < 16) ? (Wi + wrow*HH + k0) : (Wh + wrow*HH + k0 - HH);
    __half2 p0 = __halves2half2(__float2half_rn(__ldg(sw)),   __float2half_rn(__ldg(sw+1)));
    __half2 p1 = __halves2half2(__float2half_rn(__ldg(sw+8)), __float2half_rn(__ldg(sw+9)));
    wfrag[idx] = make_uint2(*(u32*)&p0, *(u32*)&p1);
  }

  // per-thread EW constants (R6 sub-block structure, j base = j0 + wc*4)
  const int q  = lane & 3;
  const int jj = (q >> 1) | ((q & 1) << 1);
  const int jg = j0 + wc*4 + jj;                 // global j of this thread
  const int b1 = b0 + wr2*16 + (lane >> 2);      // rows b1, b1+8
  float biasv[4];
  #pragma unroll
  for (int g = 0; g < 4; g++){
    int wrow = g*HH + jg;
    biasv[g] = __ldg(bih + layer*G4H + wrow) + __ldg(bhh + layer*G4H + wrow);
  }

  // ---- x -> fragment-major fp16 (once) ----
  #pragma unroll 1
  for (int u0 = 0; u0 < 4; u0++){
    int u = u0*(NBLK*NTHR) + bid*NTHR + tid;
    int t   = u >> 11;
    int kt  = (u >> 7) & 15;
    int row = u & 127;
    const float* sp = x + (t*BB + row)*HH + kt*16;
    float4 f0 = __ldg((const float4*)sp);
    float4 f1 = __ldg((const float4*)(sp+4));
    float4 f2 = __ldg((const float4*)(sp+8));
    float4 f3 = __ldg((const float4*)(sp+12));
    __half2 d0 = __halves2half2(__float2half_rn(f0.x), __float2half_rn(f0.y));
    __half2 d1 = __halves2half2(__float2half_rn(f2.x), __float2half_rn(f2.y));
    __half2 d2 = __halves2half2(__float2half_rn(f0.z), __float2half_rn(f0.w));
    __half2 d3 = __halves2half2(__float2half_rn(f2.z), __float2half_rn(f2.w));
    __half2 d4 = __halves2half2(__float2half_rn(f1.x), __float2half_rn(f1.y));
    __half2 d5 = __halves2half2(__float2half_rn(f3.x), __float2half_rn(f3.y));
    __half2 d6 = __halves2half2(__float2half_rn(f1.z), __float2half_rn(f1.w));
    __half2 d7 = __halves2half2(__float2half_rn(f3.z), __float2half_rn(f3.w));
    uint4* dst = g_xF4 + (size_t)((t*16 + kt)*128 + row)*2;
    dst[0] = make_uint4(*(u32*)&d0, *(u32*)&d1, *(u32*)&d2, *(u32*)&d3);
    dst[1] = make_uint4(*(u32*)&d4, *(u32*)&d5, *(u32*)&d6, *(u32*)&d7);
  }
  // zero parity-0 state frags + own flag
  { int idx = bid*NTHR + tid;
    if (idx < 16*BB*2){
      g_h0sF4[0][idx] = make_uint4(0,0,0,0);
      g_h1sF4[0][idx] = make_uint4(0,0,0,0);
    } }
  if (tid == 0) g_flags[bid*64] = 0u;

  unsigned base0 = 0;
  if (tid == 0) base0 = *(volatile unsigned*)&g_gen0;
  init_arrive_and_wait(base0);   // all 128 blocks; zeros + x frags visible after

  float c0 = 0.f, c1 = 0.f, hk0 = 0.f, hk1 = 0.f;
  const int b1q = b1*4 + q, b2q = (b1+8)*4 + q;
  const int ktv = jg >> 4;
  const int fo  = fragoff(jg & 15);
  const uint2* wf = wfrag + wc*2048;

  for (int t = 0; t < TT; t++){
    float a0a[4]={0,0,0,0}, a0b[4]={0,0,0,0};
    float a1a[4]={0,0,0,0}, a1b[4]={0,0,0,0};

    if (layer == 0){
      // x half: no dependency — compute before any wait
      compute_frag((const uint2*)(g_xF4 + (size_t)t*16*128*2), wf, 0,
                   b1q, b2q, lane, a0a, a0b, a1a, a1b);
      if (t >= 1) wait_flags(own_g, (unsigned)t);        // own done t-1 (h0s)
      if (t >= 2) wait_flags(l1_g, (unsigned)(t-1));     // L1 done t-2 (h0n free)
      __syncthreads();
      compute_frag((const uint2*)g_h0sF4[t&1], wf, 16,
                   b1q, b2q, lane, a0a, a0b, a1a, a1b);
    } else {
      if (t >= 1) wait_flags(own_g, (unsigned)t);        // own done t-1 (h1s)
      __syncthreads();
      compute_frag((const uint2*)g_h1sF4[t&1], wf, 16,
                   b1q, b2q, lane, a0a, a0b, a1a, a1b);
      wait_flags(l0_g, (unsigned)(t+1));                 // L0 done t (h0n ready)
      __syncthreads();
      compute_frag((const uint2*)g_h0nF4[t&1], wf, 0,
                   b1q, b2q, lane, a0a, a0b, a1a, a1b);
    }

    float acc0[4], acc1[4];
    #pragma unroll
    for (int i = 0; i < 4; i++){ acc0[i] = a0a[i]+a0b[i]; acc1[i] = a1a[i]+a1b[i]; }

    // ---- in-register gate exchange + LSTM elementwise (R6 structure) ----
    {
      float s0 = __shfl_xor_sync(0xffffffffu, (q < 2) ? acc0[1] : acc0[0], 2);
      float s1 = __shfl_xor_sync(0xffffffffu, (q < 2) ? acc0[3] : acc0[2], 2);
      float s2 = __shfl_xor_sync(0xffffffffu, (q < 2) ? acc1[1] : acc1[0], 2);
      float s3 = __shfl_xor_sync(0xffffffffu, (q < 2) ? acc1[3] : acc1[2], 2);
      float gi0, gf0, gg0, go0, gi1, gf1, gg1, go1;
      if (q < 2){
        gi0 = acc0[0]; gf0 = s0; gg0 = acc1[0]; go0 = s2;
        gi1 = acc0[2]; gf1 = s1; gg1 = acc1[2]; go1 = s3;
      } else {
        gi0 = s0; gf0 = acc0[1]; gg0 = s2; go0 = acc1[1];
        gi1 = s1; gf1 = acc0[3]; gg1 = s3; go1 = acc1[3];
      }
      gi0 += biasv[0]; gf0 += biasv[1]; gg0 += biasv[2]; go0 += biasv[3];
      gi1 += biasv[0]; gf1 += biasv[1]; gg1 += biasv[2]; go1 += biasv[3];

      const int op0 = __ldg(ops + t*BB + b1);
      const int op1 = __ldg(ops + t*BB + b1 + 8);
      float cn0 = sigf(gf0)*c0 + sigf(gi0)*tanhf(gg0);
      float hn0 = sigf(go0)*tanhf(cn0);
      float cn1 = sigf(gf1)*c1 + sigf(gi1)*tanhf(gg1);
      float hn1 = sigf(go1)*tanhf(cn1);
      if (op0){ c0 = cn0; hk0 = hn0; }
      if (op1){ c1 = cn1; hk1 = hn1; }

      const int u0h = (ktv*128 + b1)*16 + fo;
      const int u1h = (ktv*128 + b1 + 8)*16 + fo;
      if (layer == 0){
        __half* fresh = (__half*)g_h0nF4[t&1];
        __half* keep  = (__half*)g_h0sF4[(t+1)&1];
        fresh[u0h] = __float2half_rn(hn0); fresh[u1h] = __float2half_rn(hn1);
        keep[u0h]  = __float2half_rn(hk0); keep[u1h]  = __float2half_rn(hk1);
      } else {
        float* fresh = out + t*BB*HH;
        __half* keep = (__half*)g_h1sF4[(t+1)&1];
        fresh[b1*HH + jg]     = hn0;
        fresh[(b1+8)*HH + jg] = hn1;
        keep[u0h]  = __float2half_rn(hk0); keep[u1h]  = __float2half_rn(hk1);
      }
    }

    __syncthreads();                               // all EW stores issued
    if (tid == 0) strel(&g_flags[bid*64], (unsigned)(t+1));
  }
}

extern "C" void kernel_launch(void* const* d_in, const int* in_sizes, int n_in,
                              void* d_out, int out_size)
{
  const float* x   = (const float*)d_in[0];
  const int*   ops = (const int*)  d_in[1];
  const float* Wih = (const float*)d_in[2];
  const float* Whh = (const float*)d_in[3];
  const float* bih = (const float*)d_in[4];
  const float* bhh = (const float*)d_in[5];
  float* out = (float*)d_out;
  stacklstm_h16<<<NBLK, NTHR>>>(x, ops, Wih, Whh, bih, bhh, out);
}